// round 7
// baseline (speedup 1.0000x reference)
#include <cuda_runtime.h>
#include <cuda_fp16.h>
#include <cstdint>
#include <cstddef>

// Problem constants
#define T_TOK 2048
#define D_DIM 512
#define H_DIM 2048
#define N_EXP 8
#define BM 128
#define BN 256
#define BK 32                  // K elements per chunk (2 k16 steps)
#define PAD_ROWS 3072
#define MAX_TILES 24
#define NTHREADS 512

// fp16 smem layout (uint32 words; each word = 2 halves = k-pair)
#define AS_STRIDE 20           // 16 words + 4 pad; conflict-free
#define BS_STRIDE 264          // 256 words + 8 pad
#define A_STAGE_WORDS (BM * AS_STRIDE)        // 2560
#define B_STAGE_WORDS (16 * BS_STRIDE)        // 4224
#define STAGE_WORDS (A_STAGE_WORDS + B_STAGE_WORDS)   // 6784
#define STAGES 4
#define SMEM_BYTES (STAGES * STAGE_WORDS * 4)          // 108544

// GEMM2 split-K over 64 chunks: 22/21/21
#define G2_CHUNKS 64
#define NSPLIT 3

// fp16 conversion sizes (in uint32 words)
#define NW_X  (T_TOK * D_DIM / 2)              // 524288
#define NW_PE (D_DIM * H_DIM / 2)              // 524288 per expert
#define NW_W  (N_EXP * NW_PE)                  // 4194304
#define NW_TOTAL (NW_X + 2 * NW_W)

// Scratch (device globals: allocation-free rule)
__device__ int      g_perm[PAD_ROWS];
__device__ int      g_tile_expert[MAX_TILES + 8];
__device__ uint32_t g_xh[NW_X];                      // x fp16 row-major k-pairs
__device__ uint32_t g_w1h[NW_W];                     // W1 fp16 kp-interleaved [e][kp][n]
__device__ uint32_t g_w2h[NW_W];                     // W2 fp16 kp-interleaved
__device__ uint32_t g_hh[(size_t)PAD_ROWS * (H_DIM / 2)];  // h fp16 row-major
__device__ float    g_ffn[NSPLIT][(size_t)T_TOK * D_DIM];

__device__ __forceinline__ void cp16(uint32_t dst, const void* src, bool pred) {
    int sz = pred ? 16 : 0;
    asm volatile("cp.async.cg.shared.global [%0], [%1], 16, %2;\n"
                 :: "r"(dst), "l"(src), "r"(sz));
}
__device__ __forceinline__ void cp_commit() { asm volatile("cp.async.commit_group;\n"); }
template <int N> __device__ __forceinline__ void cp_wait() {
    asm volatile("cp.async.wait_group %0;\n" :: "n"(N));
}

// fp16 m16n8k16, fp32 accum
__device__ __forceinline__ void mma16(float* c,
                                      uint32_t a0, uint32_t a1, uint32_t a2, uint32_t a3,
                                      uint32_t b0, uint32_t b1) {
    asm volatile(
        "mma.sync.aligned.m16n8k16.row.col.f32.f16.f16.f32 "
        "{%0,%1,%2,%3}, {%4,%5,%6,%7}, {%8,%9}, {%0,%1,%2,%3};\n"
        : "+f"(c[0]), "+f"(c[1]), "+f"(c[2]), "+f"(c[3])
        : "r"(a0), "r"(a1), "r"(a2), "r"(a3), "r"(b0), "r"(b1));
}

__device__ __forceinline__ uint32_t pack2(float a, float b) {
    __half2 h = __floats2half2_rn(a, b);
    return *reinterpret_cast<uint32_t*>(&h);
}

// ---------------------------------------------------------------------------
// Setup: bins -> histogram -> padded grouped permutation + tile expert table
// ---------------------------------------------------------------------------
__global__ void setup_kernel(const int* __restrict__ orig, const int* __restrict__ hmap) {
    __shared__ int cnt[N_EXP];
    __shared__ int padoff[N_EXP];
    __shared__ int scat[N_EXP];
    int tid = threadIdx.x;

    if (tid < N_EXP) cnt[tid] = 0;
    __syncthreads();

    for (int t = tid; t < T_TOK; t += 256) {
        int b = hmap[orig[t]];
        atomicAdd(&cnt[b], 1);
    }
    for (int i = tid; i < PAD_ROWS; i += 256) g_perm[i] = -1;
    if (tid < MAX_TILES + 8) g_tile_expert[tid] = -1;
    __syncthreads();

    if (tid == 0) {
        int tile = 0;
        for (int e = 0; e < N_EXP; e++) {
            padoff[e] = tile * BM;
            scat[e] = 0;
            int nt = (cnt[e] + BM - 1) / BM;
            for (int i = 0; i < nt; i++) g_tile_expert[tile++] = e;
        }
    }
    __syncthreads();

    for (int t = tid; t < T_TOK; t += 256) {
        int b = hmap[orig[t]];
        int r = atomicAdd(&scat[b], 1);
        g_perm[padoff[b] + r] = t;
    }
}

// ---------------------------------------------------------------------------
// Convert fp32 inputs to fp16 (same layouts as R6 passing version)
// ---------------------------------------------------------------------------
__global__ void convert_kernel(const float* __restrict__ x,
                               const float* __restrict__ W1,
                               const float* __restrict__ W2) {
    int id = blockIdx.x * 256 + threadIdx.x;
    if (id < NW_X) {
        const float2 v = *(const float2*)(x + (size_t)id * 2);
        g_xh[id] = pack2(v.x, v.y);
        return;
    }
    int j = id - NW_X;
    if (j < NW_W) {
        int e = j >> 19;
        int kp = (j >> 11) & 255;
        int n = j & 2047;
        const float* base = W1 + (size_t)e * D_DIM * H_DIM + (size_t)(2 * kp) * H_DIM + n;
        g_w1h[j] = pack2(base[0], base[H_DIM]);
        return;
    }
    j -= NW_W;
    if (j < NW_W) {
        int e = j >> 19;
        int kp = (j >> 9) & 1023;
        int n = j & 511;
        const float* base = W2 + (size_t)e * H_DIM * D_DIM + (size_t)(2 * kp) * D_DIM + n;
        g_w2h[j] = pack2(base[0], base[D_DIM]);
    }
}

// ---------------------------------------------------------------------------
// Warp compute on one stage: warp tile 32x64, 2 k16 steps
// ---------------------------------------------------------------------------
__device__ __forceinline__ void compute_stage(const uint32_t* As, const uint32_t* Bs,
                                              float acc[2][8][4],
                                              int wm, int wn, int gid, int tig) {
#pragma unroll
    for (int s = 0; s < 2; ++s) {
        int k0 = s * 8;
        uint32_t af[2][4], bf[8][2];
#pragma unroll
        for (int mi = 0; mi < 2; ++mi) {
            int r0 = wm * 32 + mi * 16 + gid;
            af[mi][0] = As[r0 * AS_STRIDE + k0 + tig];
            af[mi][1] = As[(r0 + 8) * AS_STRIDE + k0 + tig];
            af[mi][2] = As[r0 * AS_STRIDE + k0 + tig + 4];
            af[mi][3] = As[(r0 + 8) * AS_STRIDE + k0 + tig + 4];
        }
#pragma unroll
        for (int ni = 0; ni < 8; ++ni) {
            int cb = wn * 64 + ni * 8 + gid;
            bf[ni][0] = Bs[(k0 + tig) * BS_STRIDE + cb];
            bf[ni][1] = Bs[(k0 + tig + 4) * BS_STRIDE + cb];
        }
#pragma unroll
        for (int mi = 0; mi < 2; ++mi)
#pragma unroll
            for (int ni = 0; ni < 8; ++ni)
                mma16(acc[mi][ni], af[mi][0], af[mi][1], af[mi][2], af[mi][3],
                      bf[ni][0], bf[ni][1]);
    }
}

// ---------------------------------------------------------------------------
// Unified GEMM (fp16 m16n8k16, 128x256 CTA tile, 512 threads, 4-stage cp.async)
//   G1: h = relu(x[perm] @ W1[e] + b1[e]) -> g_hh (fp16)   grid (tiles, H/256)
//   G2: g_ffn[z] = h @ W2[e][ksplit] (+b2)                 grid (tiles, D/256, 3)
// ---------------------------------------------------------------------------
template <bool G1>
__global__ __launch_bounds__(NTHREADS, 1) void gemm_kernel(const float* __restrict__ bias) {
    int te = g_tile_expert[blockIdx.x];
    if (te < 0) return;

    extern __shared__ uint32_t smx[];
    __shared__ int toks[BM];

    const int tid = threadIdx.x;
    if (tid < BM) toks[tid] = g_perm[blockIdx.x * BM + tid];
    __syncthreads();

    const int ldnw = G1 ? H_DIM : D_DIM;          // B row length in words
    const int split = G1 ? 0 : blockIdx.z;
    const int nbase = blockIdx.y * BN;
    const int lane = tid & 31, wid = tid >> 5;    // 16 warps
    const int wm = wid & 3, wn = wid >> 2;        // 4M x 4N
    const int gid = lane >> 2, tig = lane & 3;

    // chunk range
    int cb0, ncb;
    if (G1) { cb0 = 0; ncb = D_DIM / BK; }                 // 16
    else {
        int base = (G2_CHUNKS / NSPLIT);                    // 21
        int extra = G2_CHUNKS - base * NSPLIT;              // 1
        cb0 = split * base + (split < extra ? split : extra);
        ncb = base + (split < extra ? 1 : 0);               // 22/21/21
    }

    const uint32_t* Wh = (G1 ? g_w1h : g_w2h) + (size_t)te * NW_PE;

    uint32_t sbase = (uint32_t)__cvta_generic_to_shared(smx);

    // A loads: 512 cp16/chunk -> 1/thread: r = tid/4, c4 = (tid%4)*4 words
    const int a_r = tid >> 2, a_c4 = (tid & 3) * 4;
    const uint32_t* a_src;
    bool a_val;
    {
        if (G1) {
            int tk = toks[a_r];
            a_val = (tk >= 0);
            a_src = g_xh + (size_t)(tk >= 0 ? tk : 0) * (D_DIM / 2) + a_c4;
        } else {
            a_val = true;
            a_src = g_hh + ((size_t)blockIdx.x * BM + a_r) * (H_DIM / 2) + a_c4;
        }
    }
    // B loads: 1024 cp16/chunk -> 2/thread; id = tid + 512j: kp = id/64, n4 = (id%64)*4
    const int b_kp = tid >> 6, b_n4 = (tid & 63) * 4;

    float acc[2][8][4];
#pragma unroll
    for (int i = 0; i < 2; i++)
#pragma unroll
        for (int j = 0; j < 8; j++)
#pragma unroll
            for (int k = 0; k < 4; k++) acc[i][j][k] = 0.f;

    auto issue = [&](int c) {   // c = local chunk index
        int kb = cb0 + c;
        uint32_t st = sbase + (uint32_t)(c % STAGES) * STAGE_WORDS * 4;
        cp16(st + (a_r * AS_STRIDE + a_c4) * 4, a_src + kb * (BK / 2), a_val);
        uint32_t bb = st + A_STAGE_WORDS * 4;
#pragma unroll
        for (int j = 0; j < 2; ++j) {
            int kp = b_kp + 8 * j;                        // 0..15
            cp16(bb + (kp * BS_STRIDE + b_n4) * 4,
                 Wh + (size_t)(kb * 16 + kp) * ldnw + nbase + b_n4, true);
        }
        cp_commit();
    };

    issue(0);
    issue(1);
    issue(2);
    for (int c = 0; c < ncb; ++c) {
        cp_wait<STAGES - 2>();
        __syncthreads();
        if (c + STAGES - 1 < ncb) issue(c + STAGES - 1);
        const uint32_t* As = smx + (c % STAGES) * STAGE_WORDS;
        const uint32_t* Bs = As + A_STAGE_WORDS;
        compute_stage(As, Bs, acc, wm, wn, gid, tig);
        // no trailing barrier: top barrier + 4-stage ring protects reuse
    }

    // ---- epilogue ----
    const float* be = bias + (size_t)te * (G1 ? H_DIM : D_DIM);
    if (G1) {
        int rowbase = blockIdx.x * BM;
#pragma unroll
        for (int ni = 0; ni < 8; ++ni) {
            int c0 = nbase + wn * 64 + ni * 8 + tig * 2;
            float bb0 = be[c0], bb1 = be[c0 + 1];
#pragma unroll
            for (int mi = 0; mi < 2; ++mi) {
                int r0 = rowbase + wm * 32 + mi * 16 + gid;
                g_hh[(size_t)r0 * (H_DIM / 2) + (c0 >> 1)] =
                    pack2(fmaxf(acc[mi][ni][0] + bb0, 0.f),
                          fmaxf(acc[mi][ni][1] + bb1, 0.f));
                g_hh[(size_t)(r0 + 8) * (H_DIM / 2) + (c0 >> 1)] =
                    pack2(fmaxf(acc[mi][ni][2] + bb0, 0.f),
                          fmaxf(acc[mi][ni][3] + bb1, 0.f));
            }
        }
    } else {
        float* dst = g_ffn[split];
#pragma unroll
        for (int ni = 0; ni < 8; ++ni) {
            int c0 = nbase + wn * 64 + ni * 8 + tig * 2;
            float bb0 = split == 0 ? be[c0] : 0.f;
            float bb1 = split == 0 ? be[c0 + 1] : 0.f;
#pragma unroll
            for (int mi = 0; mi < 2; ++mi) {
                int rl0 = wm * 32 + mi * 16 + gid;
                int tk0 = toks[rl0];
                int tk1 = toks[rl0 + 8];
                if (tk0 >= 0) {
                    float2 v;
                    v.x = acc[mi][ni][0] + bb0;
                    v.y = acc[mi][ni][1] + bb1;
                    *(float2*)(dst + (size_t)tk0 * D_DIM + c0) = v;
                }
                if (tk1 >= 0) {
                    float2 v;
                    v.x = acc[mi][ni][2] + bb0;
                    v.y = acc[mi][ni][3] + bb1;
                    *(float2*)(dst + (size_t)tk1 * D_DIM + c0) = v;
                }
            }
        }
    }
}

// ---------------------------------------------------------------------------
// Residual + LayerNorm (sums the three split-K partials)
// ---------------------------------------------------------------------------
__global__ void ln_kernel(const float* __restrict__ x,
                          const float* __restrict__ gamma,
                          const float* __restrict__ beta,
                          float* __restrict__ out) {
    int t = blockIdx.x;
    int tid = threadIdx.x;  // 128
    size_t off = (size_t)t * D_DIM + tid * 4;

    float4 xv = *(const float4*)(x + off);
    float4 f0 = *(const float4*)(g_ffn[0] + off);
    float4 f1 = *(const float4*)(g_ffn[1] + off);
    float4 f2 = *(const float4*)(g_ffn[2] + off);
    float4 z;
    z.x = xv.x + f0.x + f1.x + f2.x;
    z.y = xv.y + f0.y + f1.y + f2.y;
    z.z = xv.z + f0.z + f1.z + f2.z;
    z.w = xv.w + f0.w + f1.w + f2.w;

    float s = z.x + z.y + z.z + z.w;
    float ss = z.x * z.x + z.y * z.y + z.z * z.z + z.w * z.w;
#pragma unroll
    for (int o = 16; o > 0; o >>= 1) {
        s += __shfl_xor_sync(0xffffffffu, s, o);
        ss += __shfl_xor_sync(0xffffffffu, ss, o);
    }
    __shared__ float sm[8];
    int w = tid >> 5;
    if ((tid & 31) == 0) { sm[w] = s; sm[4 + w] = ss; }
    __syncthreads();
    s = sm[0] + sm[1] + sm[2] + sm[3];
    ss = sm[4] + sm[5] + sm[6] + sm[7];

    float mean = s * (1.f / 512.f);
    float var = ss * (1.f / 512.f) - mean * mean;
    float rstd = rsqrtf(var + 1e-5f);

    float4 gv = *(const float4*)(gamma + tid * 4);
    float4 bv = *(const float4*)(beta + tid * 4);
    float4 o4;
    o4.x = (z.x - mean) * rstd * gv.x + bv.x;
    o4.y = (z.y - mean) * rstd * gv.y + bv.y;
    o4.z = (z.z - mean) * rstd * gv.z + bv.z;
    o4.w = (z.w - mean) * rstd * gv.w + bv.w;
    *(float4*)(out + off) = o4;
}

// ---------------------------------------------------------------------------
extern "C" void kernel_launch(void* const* d_in, const int* in_sizes, int n_in,
                              void* d_out, int out_size) {
    const float* x     = (const float*)d_in[0];
    const float* W1    = (const float*)d_in[1];
    const float* b1    = (const float*)d_in[2];
    const float* W2    = (const float*)d_in[3];
    const float* b2    = (const float*)d_in[4];
    const float* gamma = (const float*)d_in[5];
    const float* beta  = (const float*)d_in[6];
    const int*   orig  = (const int*)d_in[7];
    const int*   hmap  = (const int*)d_in[8];
    float* out = (float*)d_out;

    cudaFuncSetAttribute(gemm_kernel<true>, cudaFuncAttributeMaxDynamicSharedMemorySize, SMEM_BYTES);
    cudaFuncSetAttribute(gemm_kernel<false>, cudaFuncAttributeMaxDynamicSharedMemorySize, SMEM_BYTES);

    setup_kernel<<<1, 256>>>(orig, hmap);
    convert_kernel<<<(NW_TOTAL + 255) / 256, 256>>>(x, W1, W2);
    gemm_kernel<true><<<dim3(MAX_TILES, H_DIM / BN), NTHREADS, SMEM_BYTES>>>(b1);
    gemm_kernel<false><<<dim3(MAX_TILES, D_DIM / BN, NSPLIT), NTHREADS, SMEM_BYTES>>>(b2);
    ln_kernel<<<T_TOK, 128>>>(x, gamma, beta, out);
}

// round 8
// speedup vs baseline: 1.1912x; 1.1912x over previous
#include <cuda_runtime.h>
#include <cuda_fp16.h>
#include <cstdint>
#include <cstddef>

// Problem constants
#define T_TOK 2048
#define D_DIM 512
#define H_DIM 2048
#define N_EXP 8
#define BM 128
#define BN 128
#define BK 32                  // K elements per chunk (2 k16 steps)
#define PAD_ROWS 3072
#define MAX_TILES 24
#define NTHREADS 256

// fp16 smem layout (uint32 words; each word = 2 halves = k-pair)
#define AS_STRIDE 20           // 16 words + 4 pad; conflict-free
#define BS_STRIDE 136          // 128 words + 8 pad
#define A_STAGE_WORDS (BM * AS_STRIDE)        // 2560
#define B_STAGE_WORDS (16 * BS_STRIDE)        // 2176
#define STAGE_WORDS (A_STAGE_WORDS + B_STAGE_WORDS)   // 4736
#define STAGES 4
#define SMEM_BYTES (STAGES * STAGE_WORDS * 4)          // 75776 -> 2 CTAs/SM

// GEMM2 split-K over 64 chunks: 32/32
#define G2_CHUNKS 64
#define NSPLIT 2

// fp16 conversion sizes (in uint32 words)
#define NW_X  (T_TOK * D_DIM / 2)              // 524288
#define NW_PE (D_DIM * H_DIM / 2)              // 524288 per expert
#define NW_W  (N_EXP * NW_PE)                  // 4194304
#define NW_TOTAL (NW_X + 2 * NW_W)

// Scratch (device globals: allocation-free rule)
__device__ int      g_perm[PAD_ROWS];
__device__ int      g_tile_expert[MAX_TILES + 8];
__device__ uint32_t g_xh[NW_X];                      // x fp16 row-major k-pairs
__device__ uint32_t g_w1h[NW_W];                     // W1 fp16 kp-interleaved [e][kp][n]
__device__ uint32_t g_w2h[NW_W];                     // W2 fp16 kp-interleaved
__device__ uint32_t g_hh[(size_t)PAD_ROWS * (H_DIM / 2)];  // h fp16 row-major
__device__ float    g_ffn[NSPLIT][(size_t)T_TOK * D_DIM];

__device__ __forceinline__ void cp16(uint32_t dst, const void* src, bool pred) {
    int sz = pred ? 16 : 0;
    asm volatile("cp.async.cg.shared.global [%0], [%1], 16, %2;\n"
                 :: "r"(dst), "l"(src), "r"(sz));
}
__device__ __forceinline__ void cp_commit() { asm volatile("cp.async.commit_group;\n"); }
template <int N> __device__ __forceinline__ void cp_wait() {
    asm volatile("cp.async.wait_group %0;\n" :: "n"(N));
}

// fp16 m16n8k16, fp32 accum
__device__ __forceinline__ void mma16(float* c,
                                      uint32_t a0, uint32_t a1, uint32_t a2, uint32_t a3,
                                      uint32_t b0, uint32_t b1) {
    asm volatile(
        "mma.sync.aligned.m16n8k16.row.col.f32.f16.f16.f32 "
        "{%0,%1,%2,%3}, {%4,%5,%6,%7}, {%8,%9}, {%0,%1,%2,%3};\n"
        : "+f"(c[0]), "+f"(c[1]), "+f"(c[2]), "+f"(c[3])
        : "r"(a0), "r"(a1), "r"(a2), "r"(a3), "r"(b0), "r"(b1));
}

__device__ __forceinline__ uint32_t pack2(float a, float b) {
    __half2 h = __floats2half2_rn(a, b);
    return *reinterpret_cast<uint32_t*>(&h);
}

// ---------------------------------------------------------------------------
// Setup: bins -> histogram -> padded grouped permutation + tile expert table
// ---------------------------------------------------------------------------
__global__ void setup_kernel(const int* __restrict__ orig, const int* __restrict__ hmap) {
    __shared__ int cnt[N_EXP];
    __shared__ int padoff[N_EXP];
    __shared__ int scat[N_EXP];
    int tid = threadIdx.x;

    if (tid < N_EXP) cnt[tid] = 0;
    __syncthreads();

    for (int t = tid; t < T_TOK; t += 256) {
        int b = hmap[orig[t]];
        atomicAdd(&cnt[b], 1);
    }
    for (int i = tid; i < PAD_ROWS; i += 256) g_perm[i] = -1;
    if (tid < MAX_TILES + 8) g_tile_expert[tid] = -1;
    __syncthreads();

    if (tid == 0) {
        int tile = 0;
        for (int e = 0; e < N_EXP; e++) {
            padoff[e] = tile * BM;
            scat[e] = 0;
            int nt = (cnt[e] + BM - 1) / BM;
            for (int i = 0; i < nt; i++) g_tile_expert[tile++] = e;
        }
    }
    __syncthreads();

    for (int t = tid; t < T_TOK; t += 256) {
        int b = hmap[orig[t]];
        int r = atomicAdd(&scat[b], 1);
        g_perm[padoff[b] + r] = t;
    }
}

// ---------------------------------------------------------------------------
// Convert fp32 inputs to fp16 (layouts proven in R6)
// ---------------------------------------------------------------------------
__global__ void convert_kernel(const float* __restrict__ x,
                               const float* __restrict__ W1,
                               const float* __restrict__ W2) {
    int id = blockIdx.x * 256 + threadIdx.x;
    if (id < NW_X) {
        const float2 v = *(const float2*)(x + (size_t)id * 2);
        g_xh[id] = pack2(v.x, v.y);
        return;
    }
    int j = id - NW_X;
    if (j < NW_W) {
        int e = j >> 19;
        int kp = (j >> 11) & 255;
        int n = j & 2047;
        const float* base = W1 + (size_t)e * D_DIM * H_DIM + (size_t)(2 * kp) * H_DIM + n;
        g_w1h[j] = pack2(base[0], base[H_DIM]);
        return;
    }
    j -= NW_W;
    if (j < NW_W) {
        int e = j >> 19;
        int kp = (j >> 9) & 1023;
        int n = j & 511;
        const float* base = W2 + (size_t)e * H_DIM * D_DIM + (size_t)(2 * kp) * D_DIM + n;
        g_w2h[j] = pack2(base[0], base[D_DIM]);
    }
}

// ---------------------------------------------------------------------------
// Warp compute on one stage: warp tile 64x32, 2 k16 steps
// ---------------------------------------------------------------------------
__device__ __forceinline__ void compute_stage(const uint32_t* As, const uint32_t* Bs,
                                              float acc[4][4][4],
                                              int wm, int wn, int gid, int tig) {
#pragma unroll
    for (int s = 0; s < 2; ++s) {
        int k0 = s * 8;
        uint32_t af[4][4], bf[4][2];
#pragma unroll
        for (int mi = 0; mi < 4; ++mi) {
            int r0 = wm * 64 + mi * 16 + gid;
            af[mi][0] = As[r0 * AS_STRIDE + k0 + tig];
            af[mi][1] = As[(r0 + 8) * AS_STRIDE + k0 + tig];
            af[mi][2] = As[r0 * AS_STRIDE + k0 + tig + 4];
            af[mi][3] = As[(r0 + 8) * AS_STRIDE + k0 + tig + 4];
        }
#pragma unroll
        for (int ni = 0; ni < 4; ++ni) {
            int cb = wn * 32 + ni * 8 + gid;
            bf[ni][0] = Bs[(k0 + tig) * BS_STRIDE + cb];
            bf[ni][1] = Bs[(k0 + tig + 4) * BS_STRIDE + cb];
        }
#pragma unroll
        for (int mi = 0; mi < 4; ++mi)
#pragma unroll
            for (int ni = 0; ni < 4; ++ni)
                mma16(acc[mi][ni], af[mi][0], af[mi][1], af[mi][2], af[mi][3],
                      bf[ni][0], bf[ni][1]);
    }
}

// ---------------------------------------------------------------------------
// Unified GEMM (fp16 m16n8k16, 128x128 CTA tile, 256 threads, 4-stage cp.async,
// 2 CTAs/SM)
//   G1: h = relu(x[perm] @ W1[e] + b1[e]) -> g_hh (fp16)   grid (tiles, H/128)
//   G2: g_ffn[z] = h @ W2[e][ksplit] (+b2)                 grid (tiles, D/128, 2)
// ---------------------------------------------------------------------------
template <bool G1>
__global__ __launch_bounds__(NTHREADS, 2) void gemm_kernel(const float* __restrict__ bias) {
    int te = g_tile_expert[blockIdx.x];
    if (te < 0) return;

    extern __shared__ uint32_t smx[];
    __shared__ int toks[BM];

    const int tid = threadIdx.x;
    if (tid < BM) toks[tid] = g_perm[blockIdx.x * BM + tid];
    __syncthreads();

    const int ldnw = G1 ? H_DIM : D_DIM;          // B row length in words
    const int split = G1 ? 0 : blockIdx.z;
    const int nbase = blockIdx.y * BN;
    const int lane = tid & 31, wid = tid >> 5;    // 8 warps
    const int wm = wid & 1, wn = wid >> 1;        // 2M x 4N
    const int gid = lane >> 2, tig = lane & 3;

    // chunk range
    int cb0, ncb;
    if (G1) { cb0 = 0; ncb = D_DIM / BK; }                 // 16
    else    { cb0 = split * (G2_CHUNKS / NSPLIT); ncb = G2_CHUNKS / NSPLIT; }  // 32

    const uint32_t* Wh = (G1 ? g_w1h : g_w2h) + (size_t)te * NW_PE;

    uint32_t sbase = (uint32_t)__cvta_generic_to_shared(smx);

    // A loads: 512 cp16/chunk -> 2/thread; r = tid/4 + 64j, c4 = (tid%4)*4 words
    const int a_r = tid >> 2, a_c4 = (tid & 3) * 4;
    const uint32_t* a_src[2]; bool a_val[2];
#pragma unroll
    for (int j = 0; j < 2; ++j) {
        int r = a_r + 64 * j;
        if (G1) {
            int tk = toks[r];
            a_val[j] = (tk >= 0);
            a_src[j] = g_xh + (size_t)(tk >= 0 ? tk : 0) * (D_DIM / 2) + a_c4;
        } else {
            a_val[j] = true;
            a_src[j] = g_hh + ((size_t)blockIdx.x * BM + r) * (H_DIM / 2) + a_c4;
        }
    }
    // B loads: 512 cp16/chunk -> 2/thread; kp = tid/32 + 8j, n4 = (tid%32)*4
    const int b_kp = tid >> 5, b_n4 = (tid & 31) * 4;

    float acc[4][4][4];
#pragma unroll
    for (int i = 0; i < 4; i++)
#pragma unroll
        for (int j = 0; j < 4; j++)
#pragma unroll
            for (int k = 0; k < 4; k++) acc[i][j][k] = 0.f;

    auto issue = [&](int c) {   // c = local chunk index
        int kb = cb0 + c;
        uint32_t st = sbase + (uint32_t)(c % STAGES) * STAGE_WORDS * 4;
#pragma unroll
        for (int j = 0; j < 2; ++j)
            cp16(st + ((a_r + 64 * j) * AS_STRIDE + a_c4) * 4,
                 a_src[j] + kb * (BK / 2), a_val[j]);
        uint32_t bb = st + A_STAGE_WORDS * 4;
#pragma unroll
        for (int j = 0; j < 2; ++j) {
            int kp = b_kp + 8 * j;                        // 0..15
            cp16(bb + (kp * BS_STRIDE + b_n4) * 4,
                 Wh + (size_t)(kb * 16 + kp) * ldnw + nbase + b_n4, true);
        }
        cp_commit();
    };

    issue(0);
    issue(1);
    issue(2);
    for (int c = 0; c < ncb; ++c) {
        cp_wait<STAGES - 2>();
        __syncthreads();
        if (c + STAGES - 1 < ncb) issue(c + STAGES - 1);
        const uint32_t* As = smx + (c % STAGES) * STAGE_WORDS;
        const uint32_t* Bs = As + A_STAGE_WORDS;
        compute_stage(As, Bs, acc, wm, wn, gid, tig);
        __syncthreads();
    }

    // ---- epilogue ----
    const float* be = bias + (size_t)te * (G1 ? H_DIM : D_DIM);
    if (G1) {
        int rowbase = blockIdx.x * BM;
#pragma unroll
        for (int ni = 0; ni < 4; ++ni) {
            int c0 = nbase + wn * 32 + ni * 8 + tig * 2;
            float bb0 = be[c0], bb1 = be[c0 + 1];
#pragma unroll
            for (int mi = 0; mi < 4; ++mi) {
                int r0 = rowbase + wm * 64 + mi * 16 + gid;
                g_hh[(size_t)r0 * (H_DIM / 2) + (c0 >> 1)] =
                    pack2(fmaxf(acc[mi][ni][0] + bb0, 0.f),
                          fmaxf(acc[mi][ni][1] + bb1, 0.f));
                g_hh[(size_t)(r0 + 8) * (H_DIM / 2) + (c0 >> 1)] =
                    pack2(fmaxf(acc[mi][ni][2] + bb0, 0.f),
                          fmaxf(acc[mi][ni][3] + bb1, 0.f));
            }
        }
    } else {
        float* dst = g_ffn[split];
#pragma unroll
        for (int ni = 0; ni < 4; ++ni) {
            int c0 = nbase + wn * 32 + ni * 8 + tig * 2;
            float bb0 = split == 0 ? be[c0] : 0.f;
            float bb1 = split == 0 ? be[c0 + 1] : 0.f;
#pragma unroll
            for (int mi = 0; mi < 4; ++mi) {
                int rl0 = wm * 64 + mi * 16 + gid;
                int tk0 = toks[rl0];
                int tk1 = toks[rl0 + 8];
                if (tk0 >= 0) {
                    float2 v;
                    v.x = acc[mi][ni][0] + bb0;
                    v.y = acc[mi][ni][1] + bb1;
                    *(float2*)(dst + (size_t)tk0 * D_DIM + c0) = v;
                }
                if (tk1 >= 0) {
                    float2 v;
                    v.x = acc[mi][ni][2] + bb0;
                    v.y = acc[mi][ni][3] + bb1;
                    *(float2*)(dst + (size_t)tk1 * D_DIM + c0) = v;
                }
            }
        }
    }
}

// ---------------------------------------------------------------------------
// Residual + LayerNorm (sums the two split-K partials)
// ---------------------------------------------------------------------------
__global__ void ln_kernel(const float* __restrict__ x,
                          const float* __restrict__ gamma,
                          const float* __restrict__ beta,
                          float* __restrict__ out) {
    int t = blockIdx.x;
    int tid = threadIdx.x;  // 128
    size_t off = (size_t)t * D_DIM + tid * 4;

    float4 xv = *(const float4*)(x + off);
    float4 f0 = *(const float4*)(g_ffn[0] + off);
    float4 f1 = *(const float4*)(g_ffn[1] + off);
    float4 z;
    z.x = xv.x + f0.x + f1.x;
    z.y = xv.y + f0.y + f1.y;
    z.z = xv.z + f0.z + f1.z;
    z.w = xv.w + f0.w + f1.w;

    float s = z.x + z.y + z.z + z.w;
    float ss = z.x * z.x + z.y * z.y + z.z * z.z + z.w * z.w;
#pragma unroll
    for (int o = 16; o > 0; o >>= 1) {
        s += __shfl_xor_sync(0xffffffffu, s, o);
        ss += __shfl_xor_sync(0xffffffffu, ss, o);
    }
    __shared__ float sm[8];
    int w = tid >> 5;
    if ((tid & 31) == 0) { sm[w] = s; sm[4 + w] = ss; }
    __syncthreads();
    s = sm[0] + sm[1] + sm[2] + sm[3];
    ss = sm[4] + sm[5] + sm[6] + sm[7];

    float mean = s * (1.f / 512.f);
    float var = ss * (1.f / 512.f) - mean * mean;
    float rstd = rsqrtf(var + 1e-5f);

    float4 gv = *(const float4*)(gamma + tid * 4);
    float4 bv = *(const float4*)(beta + tid * 4);
    float4 o4;
    o4.x = (z.x - mean) * rstd * gv.x + bv.x;
    o4.y = (z.y - mean) * rstd * gv.y + bv.y;
    o4.z = (z.z - mean) * rstd * gv.z + bv.z;
    o4.w = (z.w - mean) * rstd * gv.w + bv.w;
    *(float4*)(out + off) = o4;
}

// ---------------------------------------------------------------------------
extern "C" void kernel_launch(void* const* d_in, const int* in_sizes, int n_in,
                              void* d_out, int out_size) {
    const float* x     = (const float*)d_in[0];
    const float* W1    = (const float*)d_in[1];
    const float* b1    = (const float*)d_in[2];
    const float* W2    = (const float*)d_in[3];
    const float* b2    = (const float*)d_in[4];
    const float* gamma = (const float*)d_in[5];
    const float* beta  = (const float*)d_in[6];
    const int*   orig  = (const int*)d_in[7];
    const int*   hmap  = (const int*)d_in[8];
    float* out = (float*)d_out;

    cudaFuncSetAttribute(gemm_kernel<true>, cudaFuncAttributeMaxDynamicSharedMemorySize, SMEM_BYTES);
    cudaFuncSetAttribute(gemm_kernel<false>, cudaFuncAttributeMaxDynamicSharedMemorySize, SMEM_BYTES);

    setup_kernel<<<1, 256>>>(orig, hmap);
    convert_kernel<<<(NW_TOTAL + 255) / 256, 256>>>(x, W1, W2);
    gemm_kernel<true><<<dim3(MAX_TILES, H_DIM / BN), NTHREADS, SMEM_BYTES>>>(b1);
    gemm_kernel<false><<<dim3(MAX_TILES, D_DIM / BN, NSPLIT), NTHREADS, SMEM_BYTES>>>(b2);
    ln_kernel<<<T_TOK, 128>>>(x, gamma, beta, out);
}

// round 9
// speedup vs baseline: 1.4105x; 1.1841x over previous
#include <cuda_runtime.h>
#include <cuda_fp16.h>
#include <cstdint>
#include <cstddef>

// Problem constants
#define T_TOK 2048
#define D_DIM 512
#define H_DIM 2048
#define N_EXP 8
#define BM 128
#define BN 256
#define BK 32                  // K halves per chunk (2 k16 steps)
#define PAD_ROWS 3072
#define MAX_TILES 24
#define NTHREADS 256

// smem layout (halves)
#define A_ROW_H 24             // 32 k-halves... 32? chunk=32 halves? see below
// NOTE: chunk holds 32 k-halves per A row: row = 32 halves + pad -> use 40
#undef A_ROW_H
#define A_ROW_H 40             // 32 halves + 8 pad (80B rows, 16B aligned)
#define B_ROW_H 264            // 256 n-halves + 8 pad (528B rows)
#define A_STAGE_BYTES (BM * A_ROW_H * 2)      // 10240
#define B_STAGE_BYTES (BK * B_ROW_H * 2)      // 16896
#define STAGE_BYTES (A_STAGE_BYTES + B_STAGE_BYTES)   // 27136
#define STAGES 4
#define SMEM_BYTES (STAGES * STAGE_BYTES)              // 108544

// GEMM2 split-K over 64 chunks: 22/21/21
#define G2_CHUNKS 64
#define NSPLIT 3

// fp16 sizes in uint32 words (linear pair-packed)
#define NW_X  (T_TOK * D_DIM / 2)
#define NW_PE (D_DIM * H_DIM / 2)
#define NW_W  (N_EXP * NW_PE)
#define NW_TOTAL (NW_X + 2 * NW_W)

// Scratch
__device__ int      g_perm[PAD_ROWS];
__device__ int      g_tile_expert[MAX_TILES + 8];
__device__ uint32_t g_xh[NW_X];                      // x fp16 [t][k] pair-packed
__device__ uint32_t g_w1h[NW_W];                     // W1 fp16 [e][k][n] linear
__device__ uint32_t g_w2h[NW_W];                     // W2 fp16 [e][k][n] linear
__device__ uint32_t g_hh[(size_t)PAD_ROWS * (H_DIM / 2)];  // h fp16 [row][k]
__device__ float    g_ffn[NSPLIT][(size_t)T_TOK * D_DIM];

__device__ __forceinline__ void cp16(uint32_t dst, const void* src, bool pred) {
    int sz = pred ? 16 : 0;
    asm volatile("cp.async.cg.shared.global [%0], [%1], 16, %2;\n"
                 :: "r"(dst), "l"(src), "r"(sz));
}
__device__ __forceinline__ void cp_commit() { asm volatile("cp.async.commit_group;\n"); }
template <int N> __device__ __forceinline__ void cp_wait() {
    asm volatile("cp.async.wait_group %0;\n" :: "n"(N));
}

__device__ __forceinline__ void ldsm4(uint32_t* r, uint32_t a) {
    asm volatile("ldmatrix.sync.aligned.m8n8.x4.shared.b16 {%0,%1,%2,%3}, [%4];"
                 : "=r"(r[0]), "=r"(r[1]), "=r"(r[2]), "=r"(r[3]) : "r"(a));
}
__device__ __forceinline__ void ldsm4t(uint32_t* r, uint32_t a) {
    asm volatile("ldmatrix.sync.aligned.m8n8.x4.trans.shared.b16 {%0,%1,%2,%3}, [%4];"
                 : "=r"(r[0]), "=r"(r[1]), "=r"(r[2]), "=r"(r[3]) : "r"(a));
}

__device__ __forceinline__ void mma16(float* c,
                                      uint32_t a0, uint32_t a1, uint32_t a2, uint32_t a3,
                                      uint32_t b0, uint32_t b1) {
    asm volatile(
        "mma.sync.aligned.m16n8k16.row.col.f32.f16.f16.f32 "
        "{%0,%1,%2,%3}, {%4,%5,%6,%7}, {%8,%9}, {%0,%1,%2,%3};\n"
        : "+f"(c[0]), "+f"(c[1]), "+f"(c[2]), "+f"(c[3])
        : "r"(a0), "r"(a1), "r"(a2), "r"(a3), "r"(b0), "r"(b1));
}

__device__ __forceinline__ uint32_t pack2(float a, float b) {
    __half2 h = __floats2half2_rn(a, b);
    return *reinterpret_cast<uint32_t*>(&h);
}

// ---------------------------------------------------------------------------
// Setup
// ---------------------------------------------------------------------------
__global__ void setup_kernel(const int* __restrict__ orig, const int* __restrict__ hmap) {
    __shared__ int cnt[N_EXP];
    __shared__ int padoff[N_EXP];
    __shared__ int scat[N_EXP];
    int tid = threadIdx.x;

    if (tid < N_EXP) cnt[tid] = 0;
    __syncthreads();

    for (int t = tid; t < T_TOK; t += 256) {
        int b = hmap[orig[t]];
        atomicAdd(&cnt[b], 1);
    }
    for (int i = tid; i < PAD_ROWS; i += 256) g_perm[i] = -1;
    if (tid < MAX_TILES + 8) g_tile_expert[tid] = -1;
    __syncthreads();

    if (tid == 0) {
        int tile = 0;
        for (int e = 0; e < N_EXP; e++) {
            padoff[e] = tile * BM;
            scat[e] = 0;
            int nt = (cnt[e] + BM - 1) / BM;
            for (int i = 0; i < nt; i++) g_tile_expert[tile++] = e;
        }
    }
    __syncthreads();

    for (int t = tid; t < T_TOK; t += 256) {
        int b = hmap[orig[t]];
        int r = atomicAdd(&scat[b], 1);
        g_perm[padoff[b] + r] = t;
    }
}

// ---------------------------------------------------------------------------
// Convert: pure linear fp32 -> fp16 pair pack (fully coalesced)
// ---------------------------------------------------------------------------
__global__ void convert_kernel(const float* __restrict__ x,
                               const float* __restrict__ W1,
                               const float* __restrict__ W2) {
    int id = blockIdx.x * 256 + threadIdx.x;
    if (id < NW_X) {
        const float2 v = *((const float2*)x + id);
        g_xh[id] = pack2(v.x, v.y);
        return;
    }
    int j = id - NW_X;
    if (j < NW_W) {
        const float2 v = *((const float2*)W1 + j);
        g_w1h[j] = pack2(v.x, v.y);
        return;
    }
    j -= NW_W;
    if (j < NW_W) {
        const float2 v = *((const float2*)W2 + j);
        g_w2h[j] = pack2(v.x, v.y);
    }
}

// ---------------------------------------------------------------------------
// Warp compute on one stage via ldmatrix: warp tile 64x64, 2 k16 steps
// A smem: 128 rows x 40 halves (32 k-halves + pad), row-major k
// B smem: 32 k-rows x 264 halves (256 n + pad)
// ---------------------------------------------------------------------------
__device__ __forceinline__ void compute_stage(uint32_t Abase, uint32_t Bbase,
                                              float acc[4][8][4],
                                              int wm, int wn,
                                              uint32_t a_lane_off, uint32_t b_lane_off) {
#pragma unroll
    for (int s = 0; s < 2; ++s) {
        uint32_t af[4][4];
#pragma unroll
        for (int mi = 0; mi < 4; ++mi) {
            uint32_t addr = Abase + ((wm * 64 + mi * 16) * A_ROW_H + s * 16) * 2 + a_lane_off;
            ldsm4(af[mi], addr);
        }
#pragma unroll
        for (int p = 0; p < 4; ++p) {
            uint32_t br[4];
            uint32_t addr = Bbase + (s * 16 * B_ROW_H + wn * 64 + p * 16) * 2 + b_lane_off;
            ldsm4t(br, addr);
            // br: {b0[n=2p], b1[n=2p], b0[n=2p+1], b1[n=2p+1]}
#pragma unroll
            for (int mi = 0; mi < 4; ++mi) {
                mma16(acc[mi][2 * p],     af[mi][0], af[mi][1], af[mi][2], af[mi][3], br[0], br[1]);
                mma16(acc[mi][2 * p + 1], af[mi][0], af[mi][1], af[mi][2], af[mi][3], br[2], br[3]);
            }
        }
    }
}

// ---------------------------------------------------------------------------
// Unified GEMM (fp16 m16n8k16 + ldmatrix, 128x256 tile, 256 thr, 4 stages)
//   G1: h = relu(x[perm] @ W1[e] + b1[e]) -> g_hh   grid (tiles, H/256)
//   G2: g_ffn[z] = h @ W2[e][ksplit] (+b2)          grid (tiles, D/256, 3)
// ---------------------------------------------------------------------------
template <bool G1>
__global__ __launch_bounds__(NTHREADS, 1) void gemm_kernel(const float* __restrict__ bias) {
    int te = g_tile_expert[blockIdx.x];
    if (te < 0) return;

    extern __shared__ uint32_t smx[];
    __shared__ int toks[BM];

    const int tid = threadIdx.x;
    if (tid < BM) toks[tid] = g_perm[blockIdx.x * BM + tid];
    __syncthreads();

    const int ldw = (G1 ? H_DIM : D_DIM) / 2;     // B row length in words
    const int split = G1 ? 0 : blockIdx.z;
    const int nbase = blockIdx.y * BN;
    const int lane = tid & 31, wid = tid >> 5;    // 8 warps
    const int wm = wid & 1, wn = wid >> 1;        // 2M x 4N
    const int gid = lane >> 2, tig = lane & 3;

    // chunk range
    int cb0, ncb;
    if (G1) { cb0 = 0; ncb = D_DIM / BK; }                 // 16
    else {
        int base = G2_CHUNKS / NSPLIT;                      // 21
        int extra = G2_CHUNKS - base * NSPLIT;              // 1
        cb0 = split * base + (split < extra ? split : extra);
        ncb = base + (split < extra ? 1 : 0);               // 22/21/21
    }

    const uint32_t* Wh = (G1 ? g_w1h : g_w2h) + (size_t)te * NW_PE;
    uint32_t sbase = (uint32_t)__cvta_generic_to_shared(smx);

    // ldmatrix per-lane offsets (bytes)
    const uint32_t a_lane_off = (((lane & 7) + ((lane >> 3) & 1) * 8) * A_ROW_H
                                 + ((lane >> 4) & 1) * 8) * 2;
    const uint32_t b_lane_off = (((lane & 7) + ((lane >> 3) & 1) * 8) * B_ROW_H
                                 + ((lane >> 4) & 1) * 8) * 2;

    // A cp.async: 512 cp16/chunk -> 2/thread; id = tid + 256j: row = id>>2, seg = id&3
    const int a_r = tid >> 2, a_seg = tid & 3;
    const uint32_t* a_src[2]; bool a_val[2];
#pragma unroll
    for (int j = 0; j < 2; ++j) {
        int r = a_r + 64 * j;
        if (G1) {
            int tk = toks[r];
            a_val[j] = (tk >= 0);
            a_src[j] = g_xh + (size_t)(tk >= 0 ? tk : 0) * (D_DIM / 2) + a_seg * 4;
        } else {
            a_val[j] = true;
            a_src[j] = g_hh + ((size_t)blockIdx.x * BM + r) * (H_DIM / 2) + a_seg * 4;
        }
    }
    // B cp.async: 1024 cp16/chunk -> 4/thread; id = tid + 256j: krow = id>>5, nseg = id&31
    const int b_kr = tid >> 5, b_ns = tid & 31;

    float acc[4][8][4];
#pragma unroll
    for (int i = 0; i < 4; i++)
#pragma unroll
        for (int j = 0; j < 8; j++)
#pragma unroll
            for (int k = 0; k < 4; k++) acc[i][j][k] = 0.f;

    auto issue = [&](int c) {
        int kb = cb0 + c;
        uint32_t st = sbase + (uint32_t)(c % STAGES) * STAGE_BYTES;
#pragma unroll
        for (int j = 0; j < 2; ++j)
            cp16(st + ((a_r + 64 * j) * A_ROW_H + a_seg * 8) * 2,
                 a_src[j] + kb * 16, a_val[j]);
        uint32_t bb = st + A_STAGE_BYTES;
#pragma unroll
        for (int j = 0; j < 4; ++j) {
            int kr = b_kr + 8 * j;                         // 0..31
            cp16(bb + (kr * B_ROW_H + b_ns * 8) * 2,
                 Wh + (size_t)(kb * 32 + kr) * ldw + (nbase >> 1) + b_ns * 4, true);
        }
        cp_commit();
    };

    issue(0);
    issue(1);
    issue(2);
    for (int c = 0; c < ncb; ++c) {
        cp_wait<STAGES - 2>();
        __syncthreads();
        if (c + STAGES - 1 < ncb) issue(c + STAGES - 1);
        uint32_t st = sbase + (uint32_t)(c % STAGES) * STAGE_BYTES;
        compute_stage(st, st + A_STAGE_BYTES, acc, wm, wn, a_lane_off, b_lane_off);
        __syncthreads();
    }

    // ---- epilogue ----
    const float* be = bias + (size_t)te * (G1 ? H_DIM : D_DIM);
    if (G1) {
        int rowbase = blockIdx.x * BM;
#pragma unroll
        for (int ni = 0; ni < 8; ++ni) {
            int c0 = nbase + wn * 64 + ni * 8 + tig * 2;
            float bb0 = be[c0], bb1 = be[c0 + 1];
#pragma unroll
            for (int mi = 0; mi < 4; ++mi) {
                int r0 = rowbase + wm * 64 + mi * 16 + gid;
                g_hh[(size_t)r0 * (H_DIM / 2) + (c0 >> 1)] =
                    pack2(fmaxf(acc[mi][ni][0] + bb0, 0.f),
                          fmaxf(acc[mi][ni][1] + bb1, 0.f));
                g_hh[(size_t)(r0 + 8) * (H_DIM / 2) + (c0 >> 1)] =
                    pack2(fmaxf(acc[mi][ni][2] + bb0, 0.f),
                          fmaxf(acc[mi][ni][3] + bb1, 0.f));
            }
        }
    } else {
        float* dst = g_ffn[split];
#pragma unroll
        for (int ni = 0; ni < 8; ++ni) {
            int c0 = nbase + wn * 64 + ni * 8 + tig * 2;
            float bb0 = split == 0 ? be[c0] : 0.f;
            float bb1 = split == 0 ? be[c0 + 1] : 0.f;
#pragma unroll
            for (int mi = 0; mi < 4; ++mi) {
                int rl0 = wm * 64 + mi * 16 + gid;
                int tk0 = toks[rl0];
                int tk1 = toks[rl0 + 8];
                if (tk0 >= 0) {
                    float2 v;
                    v.x = acc[mi][ni][0] + bb0;
                    v.y = acc[mi][ni][1] + bb1;
                    *(float2*)(dst + (size_t)tk0 * D_DIM + c0) = v;
                }
                if (tk1 >= 0) {
                    float2 v;
                    v.x = acc[mi][ni][2] + bb0;
                    v.y = acc[mi][ni][3] + bb1;
                    *(float2*)(dst + (size_t)tk1 * D_DIM + c0) = v;
                }
            }
        }
    }
}

// ---------------------------------------------------------------------------
// Residual + LayerNorm (sums three split-K partials)
// ---------------------------------------------------------------------------
__global__ void ln_kernel(const float* __restrict__ x,
                          const float* __restrict__ gamma,
                          const float* __restrict__ beta,
                          float* __restrict__ out) {
    int t = blockIdx.x;
    int tid = threadIdx.x;  // 128
    size_t off = (size_t)t * D_DIM + tid * 4;

    float4 xv = *(const float4*)(x + off);
    float4 f0 = *(const float4*)(g_ffn[0] + off);
    float4 f1 = *(const float4*)(g_ffn[1] + off);
    float4 f2 = *(const float4*)(g_ffn[2] + off);
    float4 z;
    z.x = xv.x + f0.x + f1.x + f2.x;
    z.y = xv.y + f0.y + f1.y + f2.y;
    z.z = xv.z + f0.z + f1.z + f2.z;
    z.w = xv.w + f0.w + f1.w + f2.w;

    float s = z.x + z.y + z.z + z.w;
    float ss = z.x * z.x + z.y * z.y + z.z * z.z + z.w * z.w;
#pragma unroll
    for (int o = 16; o > 0; o >>= 1) {
        s += __shfl_xor_sync(0xffffffffu, s, o);
        ss += __shfl_xor_sync(0xffffffffu, ss, o);
    }
    __shared__ float sm[8];
    int w = tid >> 5;
    if ((tid & 31) == 0) { sm[w] = s; sm[4 + w] = ss; }
    __syncthreads();
    s = sm[0] + sm[1] + sm[2] + sm[3];
    ss = sm[4] + sm[5] + sm[6] + sm[7];

    float mean = s * (1.f / 512.f);
    float var = ss * (1.f / 512.f) - mean * mean;
    float rstd = rsqrtf(var + 1e-5f);

    float4 gv = *(const float4*)(gamma + tid * 4);
    float4 bv = *(const float4*)(beta + tid * 4);
    float4 o4;
    o4.x = (z.x - mean) * rstd * gv.x + bv.x;
    o4.y = (z.y - mean) * rstd * gv.y + bv.y;
    o4.z = (z.z - mean) * rstd * gv.z + bv.z;
    o4.w = (z.w - mean) * rstd * gv.w + bv.w;
    *(float4*)(out + off) = o4;
}

// ---------------------------------------------------------------------------
extern "C" void kernel_launch(void* const* d_in, const int* in_sizes, int n_in,
                              void* d_out, int out_size) {
    const float* x     = (const float*)d_in[0];
    const float* W1    = (const float*)d_in[1];
    const float* b1    = (const float*)d_in[2];
    const float* W2    = (const float*)d_in[3];
    const float* b2    = (const float*)d_in[4];
    const float* gamma = (const float*)d_in[5];
    const float* beta  = (const float*)d_in[6];
    const int*   orig  = (const int*)d_in[7];
    const int*   hmap  = (const int*)d_in[8];
    float* out = (float*)d_out;

    cudaFuncSetAttribute(gemm_kernel<true>, cudaFuncAttributeMaxDynamicSharedMemorySize, SMEM_BYTES);
    cudaFuncSetAttribute(gemm_kernel<false>, cudaFuncAttributeMaxDynamicSharedMemorySize, SMEM_BYTES);

    setup_kernel<<<1, 256>>>(orig, hmap);
    convert_kernel<<<(NW_TOTAL + 255) / 256, 256>>>(x, W1, W2);
    gemm_kernel<true><<<dim3(MAX_TILES, H_DIM / BN), NTHREADS, SMEM_BYTES>>>(b1);
    gemm_kernel<false><<<dim3(MAX_TILES, D_DIM / BN, NSPLIT), NTHREADS, SMEM_BYTES>>>(b2);
    ln_kernel<<<T_TOK, 128>>>(x, gamma, beta, out);
}

// round 10
// speedup vs baseline: 1.4438x; 1.0236x over previous
#include <cuda_runtime.h>
#include <cuda_fp16.h>
#include <cstdint>
#include <cstddef>

// Problem constants
#define T_TOK 2048
#define D_DIM 512
#define H_DIM 2048
#define N_EXP 8
#define BM 128
#define BN 256
#define BK 64                  // K halves per chunk (4 k16 steps)
#define PAD_ROWS 3072
#define MAX_TILES 24
#define NTHREADS 256

// smem layout (halves)
#define A_ROW_H 72             // 64 k-halves + 8 pad (144B rows; 36w%32=4 -> conflict-free)
#define B_ROW_H 264            // 256 n-halves + 8 pad (528B rows; 132w%32=4)
#define A_STAGE_BYTES (BM * A_ROW_H * 2)      // 18432
#define B_STAGE_BYTES (BK * B_ROW_H * 2)      // 33792
#define STAGE_BYTES (A_STAGE_BYTES + B_STAGE_BYTES)   // 52224
#define STAGES 3
#define SMEM_BYTES (STAGES * STAGE_BYTES)              // 156672

// GEMM2 split-K over 32 chunks (BK=64): 11/11/10
#define G2_CHUNKS 32
#define NSPLIT 3

// fp16 sizes in uint32 words (linear pair-packed)
#define NW_X  (T_TOK * D_DIM / 2)
#define NW_PE (D_DIM * H_DIM / 2)
#define NW_W  (N_EXP * NW_PE)
#define NW_TOTAL (NW_X + 2 * NW_W)

// Scratch
__device__ int      g_perm[PAD_ROWS];
__device__ int      g_tile_expert[MAX_TILES + 8];
__device__ uint32_t g_xh[NW_X];                      // x fp16 [t][k] pair-packed
__device__ uint32_t g_w1h[NW_W];                     // W1 fp16 [e][k][n] linear
__device__ uint32_t g_w2h[NW_W];                     // W2 fp16 [e][k][n] linear
__device__ uint32_t g_hh[(size_t)PAD_ROWS * (H_DIM / 2)];  // h fp16 [row][k]
__device__ float    g_ffn[NSPLIT][(size_t)T_TOK * D_DIM];

__device__ __forceinline__ void cp16(uint32_t dst, const void* src, bool pred) {
    int sz = pred ? 16 : 0;
    asm volatile("cp.async.cg.shared.global [%0], [%1], 16, %2;\n"
                 :: "r"(dst), "l"(src), "r"(sz));
}
__device__ __forceinline__ void cp_commit() { asm volatile("cp.async.commit_group;\n"); }
template <int N> __device__ __forceinline__ void cp_wait() {
    asm volatile("cp.async.wait_group %0;\n" :: "n"(N));
}

__device__ __forceinline__ void ldsm4(uint32_t* r, uint32_t a) {
    asm volatile("ldmatrix.sync.aligned.m8n8.x4.shared.b16 {%0,%1,%2,%3}, [%4];"
                 : "=r"(r[0]), "=r"(r[1]), "=r"(r[2]), "=r"(r[3]) : "r"(a));
}
__device__ __forceinline__ void ldsm4t(uint32_t* r, uint32_t a) {
    asm volatile("ldmatrix.sync.aligned.m8n8.x4.trans.shared.b16 {%0,%1,%2,%3}, [%4];"
                 : "=r"(r[0]), "=r"(r[1]), "=r"(r[2]), "=r"(r[3]) : "r"(a));
}

__device__ __forceinline__ void mma16(float* c,
                                      uint32_t a0, uint32_t a1, uint32_t a2, uint32_t a3,
                                      uint32_t b0, uint32_t b1) {
    asm volatile(
        "mma.sync.aligned.m16n8k16.row.col.f32.f16.f16.f32 "
        "{%0,%1,%2,%3}, {%4,%5,%6,%7}, {%8,%9}, {%0,%1,%2,%3};\n"
        : "+f"(c[0]), "+f"(c[1]), "+f"(c[2]), "+f"(c[3])
        : "r"(a0), "r"(a1), "r"(a2), "r"(a3), "r"(b0), "r"(b1));
}

__device__ __forceinline__ uint32_t pack2(float a, float b) {
    __half2 h = __floats2half2_rn(a, b);
    return *reinterpret_cast<uint32_t*>(&h);
}

// ---------------------------------------------------------------------------
// Setup
// ---------------------------------------------------------------------------
__global__ void setup_kernel(const int* __restrict__ orig, const int* __restrict__ hmap) {
    __shared__ int cnt[N_EXP];
    __shared__ int padoff[N_EXP];
    __shared__ int scat[N_EXP];
    int tid = threadIdx.x;

    if (tid < N_EXP) cnt[tid] = 0;
    __syncthreads();

    for (int t = tid; t < T_TOK; t += 256) {
        int b = hmap[orig[t]];
        atomicAdd(&cnt[b], 1);
    }
    for (int i = tid; i < PAD_ROWS; i += 256) g_perm[i] = -1;
    if (tid < MAX_TILES + 8) g_tile_expert[tid] = -1;
    __syncthreads();

    if (tid == 0) {
        int tile = 0;
        for (int e = 0; e < N_EXP; e++) {
            padoff[e] = tile * BM;
            scat[e] = 0;
            int nt = (cnt[e] + BM - 1) / BM;
            for (int i = 0; i < nt; i++) g_tile_expert[tile++] = e;
        }
    }
    __syncthreads();

    for (int t = tid; t < T_TOK; t += 256) {
        int b = hmap[orig[t]];
        int r = atomicAdd(&scat[b], 1);
        g_perm[padoff[b] + r] = t;
    }
}

// ---------------------------------------------------------------------------
// Convert: pure linear fp32 -> fp16 pair pack (fully coalesced)
// ---------------------------------------------------------------------------
__global__ void convert_kernel(const float* __restrict__ x,
                               const float* __restrict__ W1,
                               const float* __restrict__ W2) {
    int id = blockIdx.x * 256 + threadIdx.x;
    if (id < NW_X) {
        const float2 v = *((const float2*)x + id);
        g_xh[id] = pack2(v.x, v.y);
        return;
    }
    int j = id - NW_X;
    if (j < NW_W) {
        const float2 v = *((const float2*)W1 + j);
        g_w1h[j] = pack2(v.x, v.y);
        return;
    }
    j -= NW_W;
    if (j < NW_W) {
        const float2 v = *((const float2*)W2 + j);
        g_w2h[j] = pack2(v.x, v.y);
    }
}

// ---------------------------------------------------------------------------
// Warp compute on one stage via ldmatrix: warp tile 64x64, 4 k16 steps
// ---------------------------------------------------------------------------
__device__ __forceinline__ void compute_stage(uint32_t Abase, uint32_t Bbase,
                                              float acc[4][8][4],
                                              int wm, int wn,
                                              uint32_t a_lane_off, uint32_t b_lane_off) {
#pragma unroll
    for (int s = 0; s < 4; ++s) {
        uint32_t af[4][4];
#pragma unroll
        for (int mi = 0; mi < 4; ++mi) {
            uint32_t addr = Abase + ((wm * 64 + mi * 16) * A_ROW_H + s * 16) * 2 + a_lane_off;
            ldsm4(af[mi], addr);
        }
#pragma unroll
        for (int p = 0; p < 4; ++p) {
            uint32_t br[4];
            uint32_t addr = Bbase + (s * 16 * B_ROW_H + wn * 64 + p * 16) * 2 + b_lane_off;
            ldsm4t(br, addr);
#pragma unroll
            for (int mi = 0; mi < 4; ++mi) {
                mma16(acc[mi][2 * p],     af[mi][0], af[mi][1], af[mi][2], af[mi][3], br[0], br[1]);
                mma16(acc[mi][2 * p + 1], af[mi][0], af[mi][1], af[mi][2], af[mi][3], br[2], br[3]);
            }
        }
    }
}

// ---------------------------------------------------------------------------
// Unified GEMM (fp16 m16n8k16 + ldmatrix, 128x256 tile, BK=64, 3 stages,
// ONE barrier per chunk)
//   G1: h = relu(x[perm] @ W1[e] + b1[e]) -> g_hh   grid (tiles, H/256)
//   G2: g_ffn[z] = h @ W2[e][ksplit] (+b2)          grid (tiles, D/256, 3)
// ---------------------------------------------------------------------------
template <bool G1>
__global__ __launch_bounds__(NTHREADS, 1) void gemm_kernel(const float* __restrict__ bias) {
    int te = g_tile_expert[blockIdx.x];
    if (te < 0) return;

    extern __shared__ uint32_t smx[];
    __shared__ int toks[BM];

    const int tid = threadIdx.x;
    if (tid < BM) toks[tid] = g_perm[blockIdx.x * BM + tid];
    __syncthreads();

    const int ldw = (G1 ? H_DIM : D_DIM) / 2;     // B k-row length in words
    const int split = G1 ? 0 : blockIdx.z;
    const int nbase = blockIdx.y * BN;
    const int lane = tid & 31, wid = tid >> 5;    // 8 warps
    const int wm = wid & 1, wn = wid >> 1;        // 2M x 4N
    const int gid = lane >> 2, tig = lane & 3;

    // chunk range
    int cb0, ncb;
    if (G1) { cb0 = 0; ncb = D_DIM / BK; }                 // 8
    else {
        int base = G2_CHUNKS / NSPLIT;                      // 10
        int extra = G2_CHUNKS - base * NSPLIT;              // 2
        cb0 = split * base + (split < extra ? split : extra);
        ncb = base + (split < extra ? 1 : 0);               // 11/11/10
    }

    const uint32_t* Wh = (G1 ? g_w1h : g_w2h) + (size_t)te * NW_PE;
    uint32_t sbase = (uint32_t)__cvta_generic_to_shared(smx);

    // ldmatrix per-lane offsets (bytes)
    const uint32_t a_lane_off = (((lane & 7) + ((lane >> 3) & 1) * 8) * A_ROW_H
                                 + ((lane >> 4) & 1) * 8) * 2;
    const uint32_t b_lane_off = (((lane & 7) + ((lane >> 3) & 1) * 8) * B_ROW_H
                                 + ((lane >> 4) & 1) * 8) * 2;

    // A cp.async: 1024 cp16/chunk -> 4/thread; id = tid + 256j: row = id>>3, seg = id&7
    const int a_r = tid >> 3, a_seg = tid & 7;
    const uint32_t* a_src[4]; bool a_val[4];
#pragma unroll
    for (int j = 0; j < 4; ++j) {
        int r = a_r + 32 * j;
        if (G1) {
            int tk = toks[r];
            a_val[j] = (tk >= 0);
            a_src[j] = g_xh + (size_t)(tk >= 0 ? tk : 0) * (D_DIM / 2) + a_seg * 4;
        } else {
            a_val[j] = true;
            a_src[j] = g_hh + ((size_t)blockIdx.x * BM + r) * (H_DIM / 2) + a_seg * 4;
        }
    }
    // B cp.async: 2048 cp16/chunk -> 8/thread; id = tid + 256j: kr = id>>5, ns = id&31
    const int b_kr = tid >> 5, b_ns = tid & 31;

    float acc[4][8][4];
#pragma unroll
    for (int i = 0; i < 4; i++)
#pragma unroll
        for (int j = 0; j < 8; j++)
#pragma unroll
            for (int k = 0; k < 4; k++) acc[i][j][k] = 0.f;

    auto issue = [&](int c) {
        int kb = cb0 + c;
        uint32_t st = sbase + (uint32_t)(c % STAGES) * STAGE_BYTES;
#pragma unroll
        for (int j = 0; j < 4; ++j)
            cp16(st + ((a_r + 32 * j) * A_ROW_H + a_seg * 8) * 2,
                 a_src[j] + kb * 32, a_val[j]);
        uint32_t bb = st + A_STAGE_BYTES;
#pragma unroll
        for (int j = 0; j < 8; ++j) {
            int kr = b_kr + 8 * j;                         // 0..63
            cp16(bb + (kr * B_ROW_H + b_ns * 8) * 2,
                 Wh + (size_t)(kb * 64 + kr) * ldw + (nbase >> 1) + b_ns * 4, true);
        }
        cp_commit();
    };

    issue(0);
    issue(1);
    for (int c = 0; c < ncb; ++c) {
        cp_wait<STAGES - 2>();
        __syncthreads();                         // single barrier per chunk
        if (c + STAGES - 1 < ncb) issue(c + STAGES - 1);
        uint32_t st = sbase + (uint32_t)(c % STAGES) * STAGE_BYTES;
        compute_stage(st, st + A_STAGE_BYTES, acc, wm, wn, a_lane_off, b_lane_off);
    }

    // ---- epilogue ----
    const float* be = bias + (size_t)te * (G1 ? H_DIM : D_DIM);
    if (G1) {
        int rowbase = blockIdx.x * BM;
#pragma unroll
        for (int ni = 0; ni < 8; ++ni) {
            int c0 = nbase + wn * 64 + ni * 8 + tig * 2;
            float bb0 = be[c0], bb1 = be[c0 + 1];
#pragma unroll
            for (int mi = 0; mi < 4; ++mi) {
                int r0 = rowbase + wm * 64 + mi * 16 + gid;
                g_hh[(size_t)r0 * (H_DIM / 2) + (c0 >> 1)] =
                    pack2(fmaxf(acc[mi][ni][0] + bb0, 0.f),
                          fmaxf(acc[mi][ni][1] + bb1, 0.f));
                g_hh[(size_t)(r0 + 8) * (H_DIM / 2) + (c0 >> 1)] =
                    pack2(fmaxf(acc[mi][ni][2] + bb0, 0.f),
                          fmaxf(acc[mi][ni][3] + bb1, 0.f));
            }
        }
    } else {
        float* dst = g_ffn[split];
#pragma unroll
        for (int ni = 0; ni < 8; ++ni) {
            int c0 = nbase + wn * 64 + ni * 8 + tig * 2;
            float bb0 = split == 0 ? be[c0] : 0.f;
            float bb1 = split == 0 ? be[c0 + 1] : 0.f;
#pragma unroll
            for (int mi = 0; mi < 4; ++mi) {
                int rl0 = wm * 64 + mi * 16 + gid;
                int tk0 = toks[rl0];
                int tk1 = toks[rl0 + 8];
                if (tk0 >= 0) {
                    float2 v;
                    v.x = acc[mi][ni][0] + bb0;
                    v.y = acc[mi][ni][1] + bb1;
                    *(float2*)(dst + (size_t)tk0 * D_DIM + c0) = v;
                }
                if (tk1 >= 0) {
                    float2 v;
                    v.x = acc[mi][ni][2] + bb0;
                    v.y = acc[mi][ni][3] + bb1;
                    *(float2*)(dst + (size_t)tk1 * D_DIM + c0) = v;
                }
            }
        }
    }
}

// ---------------------------------------------------------------------------
// Residual + LayerNorm (sums three split-K partials)
// ---------------------------------------------------------------------------
__global__ void ln_kernel(const float* __restrict__ x,
                          const float* __restrict__ gamma,
                          const float* __restrict__ beta,
                          float* __restrict__ out) {
    int t = blockIdx.x;
    int tid = threadIdx.x;  // 128
    size_t off = (size_t)t * D_DIM + tid * 4;

    float4 xv = *(const float4*)(x + off);
    float4 f0 = *(const float4*)(g_ffn[0] + off);
    float4 f1 = *(const float4*)(g_ffn[1] + off);
    float4 f2 = *(const float4*)(g_ffn[2] + off);
    float4 z;
    z.x = xv.x + f0.x + f1.x + f2.x;
    z.y = xv.y + f0.y + f1.y + f2.y;
    z.z = xv.z + f0.z + f1.z + f2.z;
    z.w = xv.w + f0.w + f1.w + f2.w;

    float s = z.x + z.y + z.z + z.w;
    float ss = z.x * z.x + z.y * z.y + z.z * z.z + z.w * z.w;
#pragma unroll
    for (int o = 16; o > 0; o >>= 1) {
        s += __shfl_xor_sync(0xffffffffu, s, o);
        ss += __shfl_xor_sync(0xffffffffu, ss, o);
    }
    __shared__ float sm[8];
    int w = tid >> 5;
    if ((tid & 31) == 0) { sm[w] = s; sm[4 + w] = ss; }
    __syncthreads();
    s = sm[0] + sm[1] + sm[2] + sm[3];
    ss = sm[4] + sm[5] + sm[6] + sm[7];

    float mean = s * (1.f / 512.f);
    float var = ss * (1.f / 512.f) - mean * mean;
    float rstd = rsqrtf(var + 1e-5f);

    float4 gv = *(const float4*)(gamma + tid * 4);
    float4 bv = *(const float4*)(beta + tid * 4);
    float4 o4;
    o4.x = (z.x - mean) * rstd * gv.x + bv.x;
    o4.y = (z.y - mean) * rstd * gv.y + bv.y;
    o4.z = (z.z - mean) * rstd * gv.z + bv.z;
    o4.w = (z.w - mean) * rstd * gv.w + bv.w;
    *(float4*)(out + off) = o4;
}

// ---------------------------------------------------------------------------
extern "C" void kernel_launch(void* const* d_in, const int* in_sizes, int n_in,
                              void* d_out, int out_size) {
    const float* x     = (const float*)d_in[0];
    const float* W1    = (const float*)d_in[1];
    const float* b1    = (const float*)d_in[2];
    const float* W2    = (const float*)d_in[3];
    const float* b2    = (const float*)d_in[4];
    const float* gamma = (const float*)d_in[5];
    const float* beta  = (const float*)d_in[6];
    const int*   orig  = (const int*)d_in[7];
    const int*   hmap  = (const int*)d_in[8];
    float* out = (float*)d_out;

    cudaFuncSetAttribute(gemm_kernel<true>, cudaFuncAttributeMaxDynamicSharedMemorySize, SMEM_BYTES);
    cudaFuncSetAttribute(gemm_kernel<false>, cudaFuncAttributeMaxDynamicSharedMemorySize, SMEM_BYTES);

    setup_kernel<<<1, 256>>>(orig, hmap);
    convert_kernel<<<(NW_TOTAL + 255) / 256, 256>>>(x, W1, W2);
    gemm_kernel<true><<<dim3(MAX_TILES, H_DIM / BN), NTHREADS, SMEM_BYTES>>>(b1);
    gemm_kernel<false><<<dim3(MAX_TILES, D_DIM / BN, NSPLIT), NTHREADS, SMEM_BYTES>>>(b2);
    ln_kernel<<<T_TOK, 128>>>(x, gamma, beta, out);
}

// round 11
// speedup vs baseline: 1.4551x; 1.0078x over previous
#include <cuda_runtime.h>
#include <cuda_fp16.h>
#include <cstdint>
#include <cstddef>

// Problem constants
#define T_TOK 2048
#define D_DIM 512
#define H_DIM 2048
#define N_EXP 8
#define BM 128
#define BN 256
#define BK 64                  // K halves per chunk (4 k16 steps)
#define PAD_ROWS 3072
#define MAX_TILES 24
#define NTHREADS 256

// smem layout (halves)
#define A_ROW_H 72             // 64 k-halves + 8 pad
#define B_ROW_H 264            // 256 n-halves + 8 pad
#define A_STAGE_BYTES (BM * A_ROW_H * 2)      // 18432
#define B_STAGE_BYTES (BK * B_ROW_H * 2)      // 33792
#define STAGE_BYTES (A_STAGE_BYTES + B_STAGE_BYTES)   // 52224
#define STAGES 3
#define SMEM_BYTES (STAGES * STAGE_BYTES)              // 156672

// GEMM2 split-K over 32 chunks (BK=64): 11/11/10
#define G2_CHUNKS 32
#define NSPLIT 3

// fp16 sizes in uint32 words (linear pair-packed)
#define NW_X  (T_TOK * D_DIM / 2)
#define NW_PE (D_DIM * H_DIM / 2)
#define NW_W  (N_EXP * NW_PE)
#define NW_TOTAL (NW_X + 2 * NW_W)

// Scratch
__device__ int      g_perm[PAD_ROWS];
__device__ int      g_tile_expert[MAX_TILES + 8];
__device__ uint32_t g_xh[NW_X];                      // x fp16 [t][k] pair-packed
__device__ uint32_t g_w1h[NW_W];                     // W1 fp16 [e][k][n] linear
__device__ uint32_t g_w2h[NW_W];                     // W2 fp16 [e][k][n] linear
__device__ uint32_t g_hh[(size_t)PAD_ROWS * (H_DIM / 2)];  // h fp16 [row][k]
__device__ float    g_ffn[NSPLIT][(size_t)T_TOK * D_DIM];

__device__ __forceinline__ void cp16(uint32_t dst, const void* src, bool pred) {
    int sz = pred ? 16 : 0;
    asm volatile("cp.async.cg.shared.global [%0], [%1], 16, %2;\n"
                 :: "r"(dst), "l"(src), "r"(sz));
}
__device__ __forceinline__ void cp_commit() { asm volatile("cp.async.commit_group;\n"); }
template <int N> __device__ __forceinline__ void cp_wait() {
    asm volatile("cp.async.wait_group %0;\n" :: "n"(N));
}

__device__ __forceinline__ void ldsm4(uint32_t* r, uint32_t a) {
    asm volatile("ldmatrix.sync.aligned.m8n8.x4.shared.b16 {%0,%1,%2,%3}, [%4];"
                 : "=r"(r[0]), "=r"(r[1]), "=r"(r[2]), "=r"(r[3]) : "r"(a));
}
__device__ __forceinline__ void ldsm4t(uint32_t* r, uint32_t a) {
    asm volatile("ldmatrix.sync.aligned.m8n8.x4.trans.shared.b16 {%0,%1,%2,%3}, [%4];"
                 : "=r"(r[0]), "=r"(r[1]), "=r"(r[2]), "=r"(r[3]) : "r"(a));
}

// NOTE: non-volatile — pure dataflow, lets ptxas interleave with prefetch LDSMs
__device__ __forceinline__ void mma16(float* c,
                                      uint32_t a0, uint32_t a1, uint32_t a2, uint32_t a3,
                                      uint32_t b0, uint32_t b1) {
    asm("mma.sync.aligned.m16n8k16.row.col.f32.f16.f16.f32 "
        "{%0,%1,%2,%3}, {%4,%5,%6,%7}, {%8,%9}, {%0,%1,%2,%3};\n"
        : "+f"(c[0]), "+f"(c[1]), "+f"(c[2]), "+f"(c[3])
        : "r"(a0), "r"(a1), "r"(a2), "r"(a3), "r"(b0), "r"(b1));
}

__device__ __forceinline__ uint32_t pack2(float a, float b) {
    __half2 h = __floats2half2_rn(a, b);
    return *reinterpret_cast<uint32_t*>(&h);
}

// ---------------------------------------------------------------------------
// Setup
// ---------------------------------------------------------------------------
__global__ void setup_kernel(const int* __restrict__ orig, const int* __restrict__ hmap) {
    __shared__ int cnt[N_EXP];
    __shared__ int padoff[N_EXP];
    __shared__ int scat[N_EXP];
    int tid = threadIdx.x;

    if (tid < N_EXP) cnt[tid] = 0;
    __syncthreads();

    for (int t = tid; t < T_TOK; t += 256) {
        int b = hmap[orig[t]];
        atomicAdd(&cnt[b], 1);
    }
    for (int i = tid; i < PAD_ROWS; i += 256) g_perm[i] = -1;
    if (tid < MAX_TILES + 8) g_tile_expert[tid] = -1;
    __syncthreads();

    if (tid == 0) {
        int tile = 0;
        for (int e = 0; e < N_EXP; e++) {
            padoff[e] = tile * BM;
            scat[e] = 0;
            int nt = (cnt[e] + BM - 1) / BM;
            for (int i = 0; i < nt; i++) g_tile_expert[tile++] = e;
        }
    }
    __syncthreads();

    for (int t = tid; t < T_TOK; t += 256) {
        int b = hmap[orig[t]];
        int r = atomicAdd(&scat[b], 1);
        g_perm[padoff[b] + r] = t;
    }
}

// ---------------------------------------------------------------------------
// Convert: pure linear fp32 -> fp16 pair pack (fully coalesced)
// ---------------------------------------------------------------------------
__global__ void convert_kernel(const float* __restrict__ x,
                               const float* __restrict__ W1,
                               const float* __restrict__ W2) {
    int id = blockIdx.x * 256 + threadIdx.x;
    if (id < NW_X) {
        const float2 v = *((const float2*)x + id);
        g_xh[id] = pack2(v.x, v.y);
        return;
    }
    int j = id - NW_X;
    if (j < NW_W) {
        const float2 v = *((const float2*)W1 + j);
        g_w1h[j] = pack2(v.x, v.y);
        return;
    }
    j -= NW_W;
    if (j < NW_W) {
        const float2 v = *((const float2*)W2 + j);
        g_w2h[j] = pack2(v.x, v.y);
    }
}

// ---------------------------------------------------------------------------
// Warp compute on one chunk, register double-buffered (software pipelined):
// prefetch next B frag / next s-step A frags during current MMAs.
// warp tile 64x64, 4 k16 steps.
// ---------------------------------------------------------------------------
__device__ __forceinline__ void compute_stage(uint32_t Abase, uint32_t Bbase,
                                              float acc[4][8][4],
                                              int wm, int wn,
                                              uint32_t a_lane_off, uint32_t b_lane_off) {
    uint32_t af[2][4][4];
    uint32_t br[2][4];

    // preload: A frags for s=0, B frag (s=0, p=0)
#pragma unroll
    for (int mi = 0; mi < 4; ++mi)
        ldsm4(af[0][mi], Abase + ((wm * 64 + mi * 16) * A_ROW_H) * 2 + a_lane_off);
    ldsm4t(br[0], Bbase + (wn * 64) * 2 + b_lane_off);

#pragma unroll
    for (int s = 0; s < 4; ++s) {
        const int sb = s & 1;
#pragma unroll
        for (int p = 0; p < 4; ++p) {
            const int cur = p & 1;
            // prefetch next fragments while current MMAs run
            if (p < 3) {
                ldsm4t(br[(p + 1) & 1],
                       Bbase + (s * 16 * B_ROW_H + wn * 64 + (p + 1) * 16) * 2 + b_lane_off);
            } else if (s < 3) {
#pragma unroll
                for (int mi = 0; mi < 4; ++mi)
                    ldsm4(af[(s + 1) & 1][mi],
                          Abase + ((wm * 64 + mi * 16) * A_ROW_H + (s + 1) * 16) * 2 + a_lane_off);
                ldsm4t(br[0],
                       Bbase + ((s + 1) * 16 * B_ROW_H + wn * 64) * 2 + b_lane_off);
            }
#pragma unroll
            for (int mi = 0; mi < 4; ++mi) {
                mma16(acc[mi][2 * p],     af[sb][mi][0], af[sb][mi][1],
                      af[sb][mi][2], af[sb][mi][3], br[cur][0], br[cur][1]);
                mma16(acc[mi][2 * p + 1], af[sb][mi][0], af[sb][mi][1],
                      af[sb][mi][2], af[sb][mi][3], br[cur][2], br[cur][3]);
            }
        }
    }
}

// ---------------------------------------------------------------------------
// Unified GEMM (fp16 m16n8k16 + ldmatrix, 128x256 tile, BK=64, 3 stages,
// one barrier per chunk, register-pipelined fragments)
//   G1: h = relu(x[perm] @ W1[e] + b1[e]) -> g_hh   grid (tiles, H/256)
//   G2: g_ffn[z] = h @ W2[e][ksplit] (+b2)          grid (tiles, D/256, 3)
// ---------------------------------------------------------------------------
template <bool G1>
__global__ __launch_bounds__(NTHREADS, 1) void gemm_kernel(const float* __restrict__ bias) {
    int te = g_tile_expert[blockIdx.x];
    if (te < 0) return;

    extern __shared__ uint32_t smx[];
    __shared__ int toks[BM];

    const int tid = threadIdx.x;
    if (tid < BM) toks[tid] = g_perm[blockIdx.x * BM + tid];
    __syncthreads();

    const int ldw = (G1 ? H_DIM : D_DIM) / 2;     // B k-row length in words
    const int split = G1 ? 0 : blockIdx.z;
    const int nbase = blockIdx.y * BN;
    const int lane = tid & 31, wid = tid >> 5;    // 8 warps
    const int wm = wid & 1, wn = wid >> 1;        // 2M x 4N
    const int gid = lane >> 2, tig = lane & 3;

    // chunk range
    int cb0, ncb;
    if (G1) { cb0 = 0; ncb = D_DIM / BK; }                 // 8
    else {
        int base = G2_CHUNKS / NSPLIT;                      // 10
        int extra = G2_CHUNKS - base * NSPLIT;              // 2
        cb0 = split * base + (split < extra ? split : extra);
        ncb = base + (split < extra ? 1 : 0);               // 11/11/10
    }

    const uint32_t* Wh = (G1 ? g_w1h : g_w2h) + (size_t)te * NW_PE;
    uint32_t sbase = (uint32_t)__cvta_generic_to_shared(smx);

    // ldmatrix per-lane offsets (bytes)
    const uint32_t a_lane_off = (((lane & 7) + ((lane >> 3) & 1) * 8) * A_ROW_H
                                 + ((lane >> 4) & 1) * 8) * 2;
    const uint32_t b_lane_off = (((lane & 7) + ((lane >> 3) & 1) * 8) * B_ROW_H
                                 + ((lane >> 4) & 1) * 8) * 2;

    // A cp.async: 1024 cp16/chunk -> 4/thread
    const int a_r = tid >> 3, a_seg = tid & 7;
    const uint32_t* a_src[4]; bool a_val[4];
#pragma unroll
    for (int j = 0; j < 4; ++j) {
        int r = a_r + 32 * j;
        if (G1) {
            int tk = toks[r];
            a_val[j] = (tk >= 0);
            a_src[j] = g_xh + (size_t)(tk >= 0 ? tk : 0) * (D_DIM / 2) + a_seg * 4;
        } else {
            a_val[j] = true;
            a_src[j] = g_hh + ((size_t)blockIdx.x * BM + r) * (H_DIM / 2) + a_seg * 4;
        }
    }
    // B cp.async: 2048 cp16/chunk -> 8/thread
    const int b_kr = tid >> 5, b_ns = tid & 31;

    float acc[4][8][4];
#pragma unroll
    for (int i = 0; i < 4; i++)
#pragma unroll
        for (int j = 0; j < 8; j++)
#pragma unroll
            for (int k = 0; k < 4; k++) acc[i][j][k] = 0.f;

    auto issue = [&](int c) {
        int kb = cb0 + c;
        uint32_t st = sbase + (uint32_t)(c % STAGES) * STAGE_BYTES;
#pragma unroll
        for (int j = 0; j < 4; ++j)
            cp16(st + ((a_r + 32 * j) * A_ROW_H + a_seg * 8) * 2,
                 a_src[j] + kb * 32, a_val[j]);
        uint32_t bb = st + A_STAGE_BYTES;
#pragma unroll
        for (int j = 0; j < 8; ++j) {
            int kr = b_kr + 8 * j;                         // 0..63
            cp16(bb + (kr * B_ROW_H + b_ns * 8) * 2,
                 Wh + (size_t)(kb * 64 + kr) * ldw + (nbase >> 1) + b_ns * 4, true);
        }
        cp_commit();
    };

    issue(0);
    issue(1);
    for (int c = 0; c < ncb; ++c) {
        cp_wait<STAGES - 2>();
        __syncthreads();                         // single barrier per chunk
        if (c + STAGES - 1 < ncb) issue(c + STAGES - 1);
        uint32_t st = sbase + (uint32_t)(c % STAGES) * STAGE_BYTES;
        compute_stage(st, st + A_STAGE_BYTES, acc, wm, wn, a_lane_off, b_lane_off);
    }

    // ---- epilogue ----
    const float* be = bias + (size_t)te * (G1 ? H_DIM : D_DIM);
    if (G1) {
        int rowbase = blockIdx.x * BM;
#pragma unroll
        for (int ni = 0; ni < 8; ++ni) {
            int c0 = nbase + wn * 64 + ni * 8 + tig * 2;
            float bb0 = be[c0], bb1 = be[c0 + 1];
#pragma unroll
            for (int mi = 0; mi < 4; ++mi) {
                int r0 = rowbase + wm * 64 + mi * 16 + gid;
                g_hh[(size_t)r0 * (H_DIM / 2) + (c0 >> 1)] =
                    pack2(fmaxf(acc[mi][ni][0] + bb0, 0.f),
                          fmaxf(acc[mi][ni][1] + bb1, 0.f));
                g_hh[(size_t)(r0 + 8) * (H_DIM / 2) + (c0 >> 1)] =
                    pack2(fmaxf(acc[mi][ni][2] + bb0, 0.f),
                          fmaxf(acc[mi][ni][3] + bb1, 0.f));
            }
        }
    } else {
        float* dst = g_ffn[split];
#pragma unroll
        for (int ni = 0; ni < 8; ++ni) {
            int c0 = nbase + wn * 64 + ni * 8 + tig * 2;
            float bb0 = split == 0 ? be[c0] : 0.f;
            float bb1 = split == 0 ? be[c0 + 1] : 0.f;
#pragma unroll
            for (int mi = 0; mi < 4; ++mi) {
                int rl0 = wm * 64 + mi * 16 + gid;
                int tk0 = toks[rl0];
                int tk1 = toks[rl0 + 8];
                if (tk0 >= 0) {
                    float2 v;
                    v.x = acc[mi][ni][0] + bb0;
                    v.y = acc[mi][ni][1] + bb1;
                    *(float2*)(dst + (size_t)tk0 * D_DIM + c0) = v;
                }
                if (tk1 >= 0) {
                    float2 v;
                    v.x = acc[mi][ni][2] + bb0;
                    v.y = acc[mi][ni][3] + bb1;
                    *(float2*)(dst + (size_t)tk1 * D_DIM + c0) = v;
                }
            }
        }
    }
}

// ---------------------------------------------------------------------------
// Residual + LayerNorm (sums three split-K partials)
// ---------------------------------------------------------------------------
__global__ void ln_kernel(const float* __restrict__ x,
                          const float* __restrict__ gamma,
                          const float* __restrict__ beta,
                          float* __restrict__ out) {
    int t = blockIdx.x;
    int tid = threadIdx.x;  // 128
    size_t off = (size_t)t * D_DIM + tid * 4;

    float4 xv = *(const float4*)(x + off);
    float4 f0 = *(const float4*)(g_ffn[0] + off);
    float4 f1 = *(const float4*)(g_ffn[1] + off);
    float4 f2 = *(const float4*)(g_ffn[2] + off);
    float4 z;
    z.x = xv.x + f0.x + f1.x + f2.x;
    z.y = xv.y + f0.y + f1.y + f2.y;
    z.z = xv.z + f0.z + f1.z + f2.z;
    z.w = xv.w + f0.w + f1.w + f2.w;

    float s = z.x + z.y + z.z + z.w;
    float ss = z.x * z.x + z.y * z.y + z.z * z.z + z.w * z.w;
#pragma unroll
    for (int o = 16; o > 0; o >>= 1) {
        s += __shfl_xor_sync(0xffffffffu, s, o);
        ss += __shfl_xor_sync(0xffffffffu, ss, o);
    }
    __shared__ float sm[8];
    int w = tid >> 5;
    if ((tid & 31) == 0) { sm[w] = s; sm[4 + w] = ss; }
    __syncthreads();
    s = sm[0] + sm[1] + sm[2] + sm[3];
    ss = sm[4] + sm[5] + sm[6] + sm[7];

    float mean = s * (1.f / 512.f);
    float var = ss * (1.f / 512.f) - mean * mean;
    float rstd = rsqrtf(var + 1e-5f);

    float4 gv = *(const float4*)(gamma + tid * 4);
    float4 bv = *(const float4*)(beta + tid * 4);
    float4 o4;
    o4.x = (z.x - mean) * rstd * gv.x + bv.x;
    o4.y = (z.y - mean) * rstd * gv.y + bv.y;
    o4.z = (z.z - mean) * rstd * gv.z + bv.z;
    o4.w = (z.w - mean) * rstd * gv.w + bv.w;
    *(float4*)(out + off) = o4;
}

// ---------------------------------------------------------------------------
extern "C" void kernel_launch(void* const* d_in, const int* in_sizes, int n_in,
                              void* d_out, int out_size) {
    const float* x     = (const float*)d_in[0];
    const float* W1    = (const float*)d_in[1];
    const float* b1    = (const float*)d_in[2];
    const float* W2    = (const float*)d_in[3];
    const float* b2    = (const float*)d_in[4];
    const float* gamma = (const float*)d_in[5];
    const float* beta  = (const float*)d_in[6];
    const int*   orig  = (const int*)d_in[7];
    const int*   hmap  = (const int*)d_in[8];
    float* out = (float*)d_out;

    cudaFuncSetAttribute(gemm_kernel<true>, cudaFuncAttributeMaxDynamicSharedMemorySize, SMEM_BYTES);
    cudaFuncSetAttribute(gemm_kernel<false>, cudaFuncAttributeMaxDynamicSharedMemorySize, SMEM_BYTES);

    setup_kernel<<<1, 256>>>(orig, hmap);
    convert_kernel<<<(NW_TOTAL + 255) / 256, 256>>>(x, W1, W2);
    gemm_kernel<true><<<dim3(MAX_TILES, H_DIM / BN), NTHREADS, SMEM_BYTES>>>(b1);
    gemm_kernel<false><<<dim3(MAX_TILES, D_DIM / BN, NSPLIT), NTHREADS, SMEM_BYTES>>>(b2);
    ln_kernel<<<T_TOK, 128>>>(x, gamma, beta, out);
}

// round 14
// speedup vs baseline: 1.5609x; 1.0727x over previous
#include <cuda_runtime.h>
#include <cuda_fp16.h>
#include <cstdint>
#include <cstddef>

// Problem constants
#define T_TOK 2048
#define D_DIM 512
#define H_DIM 2048
#define N_EXP 8
#define BM 64
#define BN 256
#define BK 64                  // K halves per chunk (4 k16 steps)
#define PAD_ROWS 2560          // 2048 + 8*64 worst case
#define MAX_TILES 40           // 2048/64 + 8
#define NTHREADS 256

// smem layout (halves)
#define A_ROW_H 72             // 64 k-halves + 8 pad (144B rows; conflict-free)
#define B_ROW_H 264            // 256 n-halves + 8 pad (528B rows)
#define A_STAGE_BYTES (BM * A_ROW_H * 2)      // 9216
#define B_STAGE_BYTES (BK * B_ROW_H * 2)      // 33792
#define STAGE_BYTES (A_STAGE_BYTES + B_STAGE_BYTES)   // 43008
#define STAGES 3
#define SMEM_BYTES (STAGES * STAGE_BYTES)              // 129024

// GEMM2 split-K: 32 BK-chunks total -> 16/16
#define NSPLIT 2

// fp16 sizes in uint32 words (linear pair-packed)
#define NW_X  (T_TOK * D_DIM / 2)
#define NW_PE (D_DIM * H_DIM / 2)
#define NW_W  (N_EXP * NW_PE)
#define NW_TOTAL (NW_X + 2 * NW_W)

// Scratch
__device__ int      g_perm[PAD_ROWS];
__device__ int      g_tile_expert[MAX_TILES + 8];
__device__ uint32_t g_xh[NW_X];                      // x fp16 [t][k] pair-packed
__device__ uint32_t g_w1h[NW_W];                     // W1 fp16 [e][k][n] linear
__device__ uint32_t g_w2h[NW_W];                     // W2 fp16 [e][k][n] linear
__device__ uint32_t g_hh[(size_t)PAD_ROWS * (H_DIM / 2)];  // h fp16 [row][k]
__device__ float    g_ffn[NSPLIT][(size_t)T_TOK * D_DIM];

__device__ __forceinline__ void cp16(uint32_t dst, const void* src, bool pred) {
    int sz = pred ? 16 : 0;
    asm volatile("cp.async.cg.shared.global [%0], [%1], 16, %2;\n"
                 :: "r"(dst), "l"(src), "r"(sz));
}
__device__ __forceinline__ void cp_commit() { asm volatile("cp.async.commit_group;\n"); }
template <int N> __device__ __forceinline__ void cp_wait() {
    asm volatile("cp.async.wait_group %0;\n" :: "n"(N));
}

__device__ __forceinline__ void ldsm4(uint32_t* r, uint32_t a) {
    asm volatile("ldmatrix.sync.aligned.m8n8.x4.shared.b16 {%0,%1,%2,%3}, [%4];"
                 : "=r"(r[0]), "=r"(r[1]), "=r"(r[2]), "=r"(r[3]) : "r"(a));
}
__device__ __forceinline__ void ldsm4t(uint32_t* r, uint32_t a) {
    asm volatile("ldmatrix.sync.aligned.m8n8.x4.trans.shared.b16 {%0,%1,%2,%3}, [%4];"
                 : "=r"(r[0]), "=r"(r[1]), "=r"(r[2]), "=r"(r[3]) : "r"(a));
}

__device__ __forceinline__ void mma16(float* c,
                                      uint32_t a0, uint32_t a1, uint32_t a2, uint32_t a3,
                                      uint32_t b0, uint32_t b1) {
    asm("mma.sync.aligned.m16n8k16.row.col.f32.f16.f16.f32 "
        "{%0,%1,%2,%3}, {%4,%5,%6,%7}, {%8,%9}, {%0,%1,%2,%3};\n"
        : "+f"(c[0]), "+f"(c[1]), "+f"(c[2]), "+f"(c[3])
        : "r"(a0), "r"(a1), "r"(a2), "r"(a3), "r"(b0), "r"(b1));
}

__device__ __forceinline__ uint32_t pack2(float a, float b) {
    __half2 h = __floats2half2_rn(a, b);
    return *reinterpret_cast<uint32_t*>(&h);
}

// ---------------------------------------------------------------------------
// Setup: bins -> histogram -> padded (to 64) grouped permutation + tile table
// ---------------------------------------------------------------------------
__global__ void setup_kernel(const int* __restrict__ orig, const int* __restrict__ hmap) {
    __shared__ int cnt[N_EXP];
    __shared__ int padoff[N_EXP];
    __shared__ int scat[N_EXP];
    int tid = threadIdx.x;

    if (tid < N_EXP) cnt[tid] = 0;
    __syncthreads();

    for (int t = tid; t < T_TOK; t += 256) {
        int b = hmap[orig[t]];
        atomicAdd(&cnt[b], 1);
    }
    for (int i = tid; i < PAD_ROWS; i += 256) g_perm[i] = -1;
    if (tid < MAX_TILES + 8) g_tile_expert[tid] = -1;
    __syncthreads();

    if (tid == 0) {
        int tile = 0;
        for (int e = 0; e < N_EXP; e++) {
            padoff[e] = tile * BM;
            scat[e] = 0;
            int nt = (cnt[e] + BM - 1) / BM;
            for (int i = 0; i < nt; i++) g_tile_expert[tile++] = e;
        }
    }
    __syncthreads();

    for (int t = tid; t < T_TOK; t += 256) {
        int b = hmap[orig[t]];
        int r = atomicAdd(&scat[b], 1);
        g_perm[padoff[b] + r] = t;
    }
}

// ---------------------------------------------------------------------------
// Convert: linear fp32 -> fp16 pair pack, float4-wide (2 words / thread)
// ---------------------------------------------------------------------------
__global__ void convert_kernel(const float* __restrict__ x,
                               const float* __restrict__ W1,
                               const float* __restrict__ W2) {
    int id = blockIdx.x * 256 + threadIdx.x;       // handles 2 words
    if (id < NW_X / 2) {
        float4 v = *((const float4*)x + id);
        uint2 o; o.x = pack2(v.x, v.y); o.y = pack2(v.z, v.w);
        *((uint2*)g_xh + id) = o;
        return;
    }
    int j = id - NW_X / 2;
    if (j < NW_W / 2) {
        float4 v = *((const float4*)W1 + j);
        uint2 o; o.x = pack2(v.x, v.y); o.y = pack2(v.z, v.w);
        *((uint2*)g_w1h + j) = o;
        return;
    }
    j -= NW_W / 2;
    if (j < NW_W / 2) {
        float4 v = *((const float4*)W2 + j);
        uint2 o; o.x = pack2(v.x, v.y); o.y = pack2(v.z, v.w);
        *((uint2*)g_w2h + j) = o;
    }
}

// ---------------------------------------------------------------------------
// Warp compute on one chunk: warp tile 32x64, 4 k16 steps
// ---------------------------------------------------------------------------
__device__ __forceinline__ void compute_stage(uint32_t Abase, uint32_t Bbase,
                                              float acc[2][8][4],
                                              int wm, int wn,
                                              uint32_t a_lane_off, uint32_t b_lane_off) {
#pragma unroll
    for (int s = 0; s < 4; ++s) {
        uint32_t af[2][4];
#pragma unroll
        for (int mi = 0; mi < 2; ++mi)
            ldsm4(af[mi], Abase + ((wm * 32 + mi * 16) * A_ROW_H + s * 16) * 2 + a_lane_off);
#pragma unroll
        for (int p = 0; p < 4; ++p) {
            uint32_t br[4];
            ldsm4t(br, Bbase + (s * 16 * B_ROW_H + wn * 64 + p * 16) * 2 + b_lane_off);
#pragma unroll
            for (int mi = 0; mi < 2; ++mi) {
                mma16(acc[mi][2 * p],     af[mi][0], af[mi][1], af[mi][2], af[mi][3], br[0], br[1]);
                mma16(acc[mi][2 * p + 1], af[mi][0], af[mi][1], af[mi][2], af[mi][3], br[2], br[3]);
            }
        }
    }
}

// ---------------------------------------------------------------------------
// Unified GEMM (fp16 m16n8k16 + ldmatrix, 64x256 tile, BK=64, 3 stages)
//   G1: h = relu(x[perm] @ W1[e] + b1[e]) -> g_hh   grid (MAX_TILES, H/256)
//   G2: g_ffn[z] = h @ W2[e][ksplit] (+b2)          grid (MAX_TILES, D/256, 2)
// ---------------------------------------------------------------------------
template <bool G1>
__global__ __launch_bounds__(NTHREADS, 1) void gemm_kernel(const float* __restrict__ bias) {
    int te = g_tile_expert[blockIdx.x];
    if (te < 0) return;

    extern __shared__ uint32_t smx[];
    __shared__ int toks[BM];

    const int tid = threadIdx.x;
    if (tid < BM) toks[tid] = g_perm[blockIdx.x * BM + tid];
    __syncthreads();

    const int ldw = (G1 ? H_DIM : D_DIM) / 2;     // B k-row length in words
    const int split = G1 ? 0 : blockIdx.z;
    const int nbase = blockIdx.y * BN;
    const int lane = tid & 31, wid = tid >> 5;    // 8 warps
    const int wm = wid & 1, wn = wid >> 1;        // 2M x 4N, warp 32x64
    const int gid = lane >> 2, tig = lane & 3;

    // chunk range: G1: 8 chunks of K=512; G2: 16 chunks of split half (K=1024)
    const int ncb = G1 ? (D_DIM / BK) : (H_DIM / BK / NSPLIT);
    const int cb0 = G1 ? 0 : split * ncb;

    const uint32_t* Wh = (G1 ? g_w1h : g_w2h) + (size_t)te * NW_PE;
    uint32_t sbase = (uint32_t)__cvta_generic_to_shared(smx);

    // ldmatrix per-lane offsets (bytes)
    const uint32_t a_lane_off = (((lane & 7) + ((lane >> 3) & 1) * 8) * A_ROW_H
                                 + ((lane >> 4) & 1) * 8) * 2;
    const uint32_t b_lane_off = (((lane & 7) + ((lane >> 3) & 1) * 8) * B_ROW_H
                                 + ((lane >> 4) & 1) * 8) * 2;

    // A cp.async: 512 cp16/chunk -> 2/thread; id = tid + 256j: r = id>>3, seg = id&7
    const int a_r = tid >> 3, a_seg = tid & 7;
    const uint32_t* a_src[2]; bool a_val[2];
#pragma unroll
    for (int j = 0; j < 2; ++j) {
        int r = a_r + 32 * j;
        if (G1) {
            int tk = toks[r];
            a_val[j] = (tk >= 0);
            a_src[j] = g_xh + (size_t)(tk >= 0 ? tk : 0) * (D_DIM / 2) + a_seg * 4;
        } else {
            a_val[j] = true;
            a_src[j] = g_hh + ((size_t)blockIdx.x * BM + r) * (H_DIM / 2) + a_seg * 4;
        }
    }
    // B cp.async: 2048 cp16/chunk -> 8/thread; kr = tid>>5 + 8j, ns = tid&31
    const int b_kr = tid >> 5, b_ns = tid & 31;

    float acc[2][8][4];
#pragma unroll
    for (int i = 0; i < 2; i++)
#pragma unroll
        for (int j = 0; j < 8; j++)
#pragma unroll
            for (int k = 0; k < 4; k++) acc[i][j][k] = 0.f;

    auto issue = [&](int c) {
        int kb = cb0 + c;
        uint32_t st = sbase + (uint32_t)(c % STAGES) * STAGE_BYTES;
#pragma unroll
        for (int j = 0; j < 2; ++j)
            cp16(st + ((a_r + 32 * j) * A_ROW_H + a_seg * 8) * 2,
                 a_src[j] + kb * 32, a_val[j]);
        uint32_t bb = st + A_STAGE_BYTES;
#pragma unroll
        for (int j = 0; j < 8; ++j) {
            int kr = b_kr + 8 * j;                         // 0..63
            cp16(bb + (kr * B_ROW_H + b_ns * 8) * 2,
                 Wh + (size_t)(kb * 64 + kr) * ldw + (nbase >> 1) + b_ns * 4, true);
        }
        cp_commit();
    };

    issue(0);
    issue(1);
    for (int c = 0; c < ncb; ++c) {
        cp_wait<STAGES - 2>();
        __syncthreads();                         // single barrier per chunk
        if (c + STAGES - 1 < ncb) issue(c + STAGES - 1);
        uint32_t st = sbase + (uint32_t)(c % STAGES) * STAGE_BYTES;
        compute_stage(st, st + A_STAGE_BYTES, acc, wm, wn, a_lane_off, b_lane_off);
    }

    // ---- epilogue ----
    const float* be = bias + (size_t)te * (G1 ? H_DIM : D_DIM);
    if (G1) {
        int rowbase = blockIdx.x * BM;
#pragma unroll
        for (int ni = 0; ni < 8; ++ni) {
            int c0 = nbase + wn * 64 + ni * 8 + tig * 2;
            float bb0 = be[c0], bb1 = be[c0 + 1];
#pragma unroll
            for (int mi = 0; mi < 2; ++mi) {
                int r0 = rowbase + wm * 32 + mi * 16 + gid;
                g_hh[(size_t)r0 * (H_DIM / 2) + (c0 >> 1)] =
                    pack2(fmaxf(acc[mi][ni][0] + bb0, 0.f),
                          fmaxf(acc[mi][ni][1] + bb1, 0.f));
                g_hh[(size_t)(r0 + 8) * (H_DIM / 2) + (c0 >> 1)] =
                    pack2(fmaxf(acc[mi][ni][2] + bb0, 0.f),
                          fmaxf(acc[mi][ni][3] + bb1, 0.f));
            }
        }
    } else {
        float* dst = g_ffn[split];
#pragma unroll
        for (int ni = 0; ni < 8; ++ni) {
            int c0 = nbase + wn * 64 + ni * 8 + tig * 2;
            float bb0 = split == 0 ? be[c0] : 0.f;
            float bb1 = split == 0 ? be[c0 + 1] : 0.f;
#pragma unroll
            for (int mi = 0; mi < 2; ++mi) {
                int rl0 = wm * 32 + mi * 16 + gid;
                int tk0 = toks[rl0];
                int tk1 = toks[rl0 + 8];
                if (tk0 >= 0) {
                    float2 v;
                    v.x = acc[mi][ni][0] + bb0;
                    v.y = acc[mi][ni][1] + bb1;
                    *(float2*)(dst + (size_t)tk0 * D_DIM + c0) = v;
                }
                if (tk1 >= 0) {
                    float2 v;
                    v.x = acc[mi][ni][2] + bb0;
                    v.y = acc[mi][ni][3] + bb1;
                    *(float2*)(dst + (size_t)tk1 * D_DIM + c0) = v;
                }
            }
        }
    }
}

// ---------------------------------------------------------------------------
// Residual + LayerNorm (sums two split-K partials)
// ---------------------------------------------------------------------------
__global__ void ln_kernel(const float* __restrict__ x,
                          const float* __restrict__ gamma,
                          const float* __restrict__ beta,
                          float* __restrict__ out) {
    int t = blockIdx.x;
    int tid = threadIdx.x;  // 128
    size_t off = (size_t)t * D_DIM + tid * 4;

    float4 xv = *(const float4*)(x + off);
    float4 f0 = *(const float4*)(g_ffn[0] + off);
    float4 f1 = *(const float4*)(g_ffn[1] + off);
    float4 z;
    z.x = xv.x + f0.x + f1.x;
    z.y = xv.y + f0.y + f1.y;
    z.z = xv.z + f0.z + f1.z;
    z.w = xv.w + f0.w + f1.w;

    float s = z.x + z.y + z.z + z.w;
    float ss = z.x * z.x + z.y * z.y + z.z * z.z + z.w * z.w;
#pragma unroll
    for (int o = 16; o > 0; o >>= 1) {
        s += __shfl_xor_sync(0xffffffffu, s, o);
        ss += __shfl_xor_sync(0xffffffffu, ss, o);
    }
    __shared__ float sm[8];
    int w = tid >> 5;
    if ((tid & 31) == 0) { sm[w] = s; sm[4 + w] = ss; }
    __syncthreads();
    s = sm[0] + sm[1] + sm[2] + sm[3];
    ss = sm[4] + sm[5] + sm[6] + sm[7];

    float mean = s * (1.f / 512.f);
    float var = ss * (1.f / 512.f) - mean * mean;
    float rstd = rsqrtf(var + 1e-5f);

    float4 gv = *(const float4*)(gamma + tid * 4);
    float4 bv = *(const float4*)(beta + tid * 4);
    float4 o4;
    o4.x = (z.x - mean) * rstd * gv.x + bv.x;
    o4.y = (z.y - mean) * rstd * gv.y + bv.y;
    o4.z = (z.z - mean) * rstd * gv.z + bv.z;
    o4.w = (z.w - mean) * rstd * gv.w + bv.w;
    *(float4*)(out + off) = o4;
}

// ---------------------------------------------------------------------------
extern "C" void kernel_launch(void* const* d_in, const int* in_sizes, int n_in,
                              void* d_out, int out_size) {
    const float* x     = (const float*)d_in[0];
    const float* W1    = (const float*)d_in[1];
    const float* b1    = (const float*)d_in[2];
    const float* W2    = (const float*)d_in[3];
    const float* b2    = (const float*)d_in[4];
    const float* gamma = (const float*)d_in[5];
    const float* beta  = (const float*)d_in[6];
    const int*   orig  = (const int*)d_in[7];
    const int*   hmap  = (const int*)d_in[8];
    float* out = (float*)d_out;

    cudaFuncSetAttribute(gemm_kernel<true>, cudaFuncAttributeMaxDynamicSharedMemorySize, SMEM_BYTES);
    cudaFuncSetAttribute(gemm_kernel<false>, cudaFuncAttributeMaxDynamicSharedMemorySize, SMEM_BYTES);

    setup_kernel<<<1, 256>>>(orig, hmap);
    convert_kernel<<<(NW_TOTAL / 2 + 255) / 256, 256>>>(x, W1, W2);
    gemm_kernel<true><<<dim3(MAX_TILES, H_DIM / BN), NTHREADS, SMEM_BYTES>>>(b1);
    gemm_kernel<false><<<dim3(MAX_TILES, D_DIM / BN, NSPLIT), NTHREADS, SMEM_BYTES>>>(b2);
    ln_kernel<<<T_TOK, 128>>>(x, gamma, beta, out);
}

// round 15
// speedup vs baseline: 1.5894x; 1.0182x over previous
#include <cuda_runtime.h>
#include <cuda_fp16.h>
#include <cstdint>
#include <cstddef>

// Problem constants
#define T_TOK 2048
#define D_DIM 512
#define H_DIM 2048
#define N_EXP 8
#define BM 64
#define BN 256
#define BK 64                  // K elements per chunk (4 k16 steps)
#define PAD_ROWS 2560
#define MAX_TILES 40
#define NTHREADS 256

// smem layout
#define A_ROW_H 72             // 64 k-halves + 8 pad (fp16)
#define B_ROW_F 260            // 256 n-floats + 4 pad (fp32)
#define A_STAGE_BYTES (BM * A_ROW_H * 2)      // 9216
#define B_STAGE_BYTES (BK * B_ROW_F * 4)      // 66560
#define STAGE_BYTES (A_STAGE_BYTES + B_STAGE_BYTES)   // 75776
#define STAGES 3
#define SMEM_BYTES (STAGES * STAGE_BYTES)              // 227328 (fits 227KB dyn)

// GEMM2 split-K: 32 BK-chunks -> 16/16
#define NSPLIT 2

#define NW_X  (T_TOK * D_DIM / 2)
#define W_PE  ((size_t)D_DIM * H_DIM)          // fp32 elems per expert (same both)

// Scratch
__device__ int      g_perm[PAD_ROWS];
__device__ int      g_tile_expert[MAX_TILES + 8];
__device__ uint32_t g_xh[NW_X];                      // x fp16 [t][k] pair-packed
__device__ uint32_t g_hh[(size_t)PAD_ROWS * (H_DIM / 2)];  // h fp16 [row][k]
__device__ float    g_ffn[NSPLIT][(size_t)T_TOK * D_DIM];

__device__ __forceinline__ void cp16(uint32_t dst, const void* src, bool pred) {
    int sz = pred ? 16 : 0;
    asm volatile("cp.async.cg.shared.global [%0], [%1], 16, %2;\n"
                 :: "r"(dst), "l"(src), "r"(sz));
}
__device__ __forceinline__ void cp_commit() { asm volatile("cp.async.commit_group;\n"); }
template <int N> __device__ __forceinline__ void cp_wait() {
    asm volatile("cp.async.wait_group %0;\n" :: "n"(N));
}

__device__ __forceinline__ void ldsm4(uint32_t* r, uint32_t a) {
    asm volatile("ldmatrix.sync.aligned.m8n8.x4.shared.b16 {%0,%1,%2,%3}, [%4];"
                 : "=r"(r[0]), "=r"(r[1]), "=r"(r[2]), "=r"(r[3]) : "r"(a));
}

__device__ __forceinline__ void mma16(float* c,
                                      uint32_t a0, uint32_t a1, uint32_t a2, uint32_t a3,
                                      uint32_t b0, uint32_t b1) {
    asm("mma.sync.aligned.m16n8k16.row.col.f32.f16.f16.f32 "
        "{%0,%1,%2,%3}, {%4,%5,%6,%7}, {%8,%9}, {%0,%1,%2,%3};\n"
        : "+f"(c[0]), "+f"(c[1]), "+f"(c[2]), "+f"(c[3])
        : "r"(a0), "r"(a1), "r"(a2), "r"(a3), "r"(b0), "r"(b1));
}

__device__ __forceinline__ uint32_t pack2(float a, float b) {
    __half2 h = __floats2half2_rn(a, b);
    return *reinterpret_cast<uint32_t*>(&h);
}

// ---------------------------------------------------------------------------
// Setup: bins -> histogram -> padded (to 64) grouped permutation + tile table
// ---------------------------------------------------------------------------
__global__ void setup_kernel(const int* __restrict__ orig, const int* __restrict__ hmap) {
    __shared__ int cnt[N_EXP];
    __shared__ int padoff[N_EXP];
    __shared__ int scat[N_EXP];
    int tid = threadIdx.x;

    if (tid < N_EXP) cnt[tid] = 0;
    __syncthreads();

    for (int t = tid; t < T_TOK; t += 256) {
        int b = hmap[orig[t]];
        atomicAdd(&cnt[b], 1);
    }
    for (int i = tid; i < PAD_ROWS; i += 256) g_perm[i] = -1;
    if (tid < MAX_TILES + 8) g_tile_expert[tid] = -1;
    __syncthreads();

    if (tid == 0) {
        int tile = 0;
        for (int e = 0; e < N_EXP; e++) {
            padoff[e] = tile * BM;
            scat[e] = 0;
            int nt = (cnt[e] + BM - 1) / BM;
            for (int i = 0; i < nt; i++) g_tile_expert[tile++] = e;
        }
    }
    __syncthreads();

    for (int t = tid; t < T_TOK; t += 256) {
        int b = hmap[orig[t]];
        int r = atomicAdd(&scat[b], 1);
        g_perm[padoff[b] + r] = t;
    }
}

// ---------------------------------------------------------------------------
// Convert x only: fp32 -> fp16 pair pack (weights stay fp32, converted in-GEMM)
// ---------------------------------------------------------------------------
__global__ void convert_x_kernel(const float* __restrict__ x) {
    int id = blockIdx.x * 256 + threadIdx.x;       // 2 words / thread
    if (id < NW_X / 2) {
        float4 v = *((const float4*)x + id);
        uint2 o; o.x = pack2(v.x, v.y); o.y = pack2(v.z, v.w);
        *((uint2*)g_xh + id) = o;
    }
}

// ---------------------------------------------------------------------------
// Warp compute on one chunk: warp tile 32x64, 4 k16 steps.
// A frags via ldmatrix (fp16 smem); B frags built manually from fp32 smem
// (LDS + cvt.rn.f16x2.f32) — replaces the weight-convert kernel.
// ---------------------------------------------------------------------------
__device__ __forceinline__ void compute_stage(uint32_t Abase, const float* Bp,
                                              float acc[2][8][4],
                                              int wm, int wn,
                                              uint32_t a_lane_off, int gid, int tig) {
#pragma unroll
    for (int s = 0; s < 4; ++s) {
        uint32_t af[2][4];
#pragma unroll
        for (int mi = 0; mi < 2; ++mi)
            ldsm4(af[mi], Abase + ((wm * 32 + mi * 16) * A_ROW_H + s * 16) * 2 + a_lane_off);
        const int k0 = s * 16;
        const float* B0 = Bp + (k0 + 2 * tig) * B_ROW_F;       // k row for b-low
        const float* B8 = B0 + 8 * B_ROW_F;                    // k row +8
#pragma unroll
        for (int p = 0; p < 4; ++p) {
            int n0 = wn * 64 + p * 16 + gid;
            uint32_t b0a = pack2(B0[n0], B0[B_ROW_F + n0]);
            uint32_t b1a = pack2(B8[n0], B8[B_ROW_F + n0]);
            uint32_t b0b = pack2(B0[n0 + 8], B0[B_ROW_F + n0 + 8]);
            uint32_t b1b = pack2(B8[n0 + 8], B8[B_ROW_F + n0 + 8]);
#pragma unroll
            for (int mi = 0; mi < 2; ++mi) {
                mma16(acc[mi][2 * p],     af[mi][0], af[mi][1], af[mi][2], af[mi][3], b0a, b1a);
                mma16(acc[mi][2 * p + 1], af[mi][0], af[mi][1], af[mi][2], af[mi][3], b0b, b1b);
            }
        }
    }
}

// ---------------------------------------------------------------------------
// Unified GEMM (fp16 m16n8k16, 64x256 tile, BK=64, 3 stages, fp32 weights)
//   G1: h = relu(x[perm] @ W1[e] + b1[e]) -> g_hh   grid (MAX_TILES, H/256)
//   G2: g_ffn[z] = h @ W2[e][ksplit] (+b2)          grid (MAX_TILES, D/256, 2)
// ---------------------------------------------------------------------------
template <bool G1>
__global__ __launch_bounds__(NTHREADS, 1) void gemm_kernel(const float* __restrict__ W,
                                                           const float* __restrict__ bias) {
    int te = g_tile_expert[blockIdx.x];
    if (te < 0) return;

    extern __shared__ uint32_t smx[];
    __shared__ int toks[BM];

    const int tid = threadIdx.x;
    if (tid < BM) toks[tid] = g_perm[blockIdx.x * BM + tid];
    __syncthreads();

    const int ldn = G1 ? H_DIM : D_DIM;           // B k-row length in floats
    const int split = G1 ? 0 : blockIdx.z;
    const int nbase = blockIdx.y * BN;
    const int lane = tid & 31, wid = tid >> 5;    // 8 warps
    const int wm = wid & 1, wn = wid >> 1;        // 2M x 4N, warp 32x64
    const int gid = lane >> 2, tig = lane & 3;

    const int ncb = G1 ? (D_DIM / BK) : (H_DIM / BK / NSPLIT);   // 8 / 16
    const int cb0 = G1 ? 0 : split * ncb;

    const float* We = W + (size_t)te * W_PE;
    uint32_t sbase = (uint32_t)__cvta_generic_to_shared(smx);

    // ldmatrix per-lane offset for A (bytes)
    const uint32_t a_lane_off = (((lane & 7) + ((lane >> 3) & 1) * 8) * A_ROW_H
                                 + ((lane >> 4) & 1) * 8) * 2;

    // A cp.async: 512 cp16/chunk -> 2/thread; r = tid>>3 (+32), seg = tid&7
    const int a_r = tid >> 3, a_seg = tid & 7;
    const uint32_t* a_src[2]; bool a_val[2];
#pragma unroll
    for (int j = 0; j < 2; ++j) {
        int r = a_r + 32 * j;
        if (G1) {
            int tk = toks[r];
            a_val[j] = (tk >= 0);
            a_src[j] = g_xh + (size_t)(tk >= 0 ? tk : 0) * (D_DIM / 2) + a_seg * 4;
        } else {
            a_val[j] = true;
            a_src[j] = g_hh + ((size_t)blockIdx.x * BM + r) * (H_DIM / 2) + a_seg * 4;
        }
    }
    // B cp.async (fp32): 4096 cp16/chunk -> 16/thread; kr = tid>>6 (+4j), ns = tid&63
    const int b_kr = tid >> 6, b_ns = tid & 63;

    float acc[2][8][4];
#pragma unroll
    for (int i = 0; i < 2; i++)
#pragma unroll
        for (int j = 0; j < 8; j++)
#pragma unroll
            for (int k = 0; k < 4; k++) acc[i][j][k] = 0.f;

    auto issue = [&](int c) {
        int kb = cb0 + c;
        uint32_t st = sbase + (uint32_t)(c % STAGES) * STAGE_BYTES;
#pragma unroll
        for (int j = 0; j < 2; ++j)
            cp16(st + ((a_r + 32 * j) * A_ROW_H + a_seg * 8) * 2,
                 a_src[j] + kb * 32, a_val[j]);
        uint32_t bb = st + A_STAGE_BYTES;
#pragma unroll
        for (int j = 0; j < 16; ++j) {
            int kr = b_kr + 4 * j;                         // 0..63
            cp16(bb + (kr * B_ROW_F + b_ns * 4) * 4,
                 We + (size_t)(kb * 64 + kr) * ldn + nbase + b_ns * 4, true);
        }
        cp_commit();
    };

    issue(0);
    issue(1);
    for (int c = 0; c < ncb; ++c) {
        cp_wait<STAGES - 2>();
        __syncthreads();                         // single barrier per chunk
        if (c + STAGES - 1 < ncb) issue(c + STAGES - 1);
        uint32_t st = sbase + (uint32_t)(c % STAGES) * STAGE_BYTES;
        const float* Bp = (const float*)((char*)smx + (c % STAGES) * STAGE_BYTES + A_STAGE_BYTES);
        compute_stage(st, Bp, acc, wm, wn, a_lane_off, gid, tig);
    }

    // ---- epilogue ----
    const float* be = bias + (size_t)te * (G1 ? H_DIM : D_DIM);
    if (G1) {
        int rowbase = blockIdx.x * BM;
#pragma unroll
        for (int ni = 0; ni < 8; ++ni) {
            int c0 = nbase + wn * 64 + ni * 8 + tig * 2;
            float bb0 = be[c0], bb1 = be[c0 + 1];
#pragma unroll
            for (int mi = 0; mi < 2; ++mi) {
                int r0 = rowbase + wm * 32 + mi * 16 + gid;
                g_hh[(size_t)r0 * (H_DIM / 2) + (c0 >> 1)] =
                    pack2(fmaxf(acc[mi][ni][0] + bb0, 0.f),
                          fmaxf(acc[mi][ni][1] + bb1, 0.f));
                g_hh[(size_t)(r0 + 8) * (H_DIM / 2) + (c0 >> 1)] =
                    pack2(fmaxf(acc[mi][ni][2] + bb0, 0.f),
                          fmaxf(acc[mi][ni][3] + bb1, 0.f));
            }
        }
    } else {
        float* dst = g_ffn[split];
#pragma unroll
        for (int ni = 0; ni < 8; ++ni) {
            int c0 = nbase + wn * 64 + ni * 8 + tig * 2;
            float bb0 = split == 0 ? be[c0] : 0.f;
            float bb1 = split == 0 ? be[c0 + 1] : 0.f;
#pragma unroll
            for (int mi = 0; mi < 2; ++mi) {
                int rl0 = wm * 32 + mi * 16 + gid;
                int tk0 = toks[rl0];
                int tk1 = toks[rl0 + 8];
                if (tk0 >= 0) {
                    float2 v;
                    v.x = acc[mi][ni][0] + bb0;
                    v.y = acc[mi][ni][1] + bb1;
                    *(float2*)(dst + (size_t)tk0 * D_DIM + c0) = v;
                }
                if (tk1 >= 0) {
                    float2 v;
                    v.x = acc[mi][ni][2] + bb0;
                    v.y = acc[mi][ni][3] + bb1;
                    *(float2*)(dst + (size_t)tk1 * D_DIM + c0) = v;
                }
            }
        }
    }
}

// ---------------------------------------------------------------------------
// Residual + LayerNorm (sums two split-K partials)
// ---------------------------------------------------------------------------
__global__ void ln_kernel(const float* __restrict__ x,
                          const float* __restrict__ gamma,
                          const float* __restrict__ beta,
                          float* __restrict__ out) {
    int t = blockIdx.x;
    int tid = threadIdx.x;  // 128
    size_t off = (size_t)t * D_DIM + tid * 4;

    float4 xv = *(const float4*)(x + off);
    float4 f0 = *(const float4*)(g_ffn[0] + off);
    float4 f1 = *(const float4*)(g_ffn[1] + off);
    float4 z;
    z.x = xv.x + f0.x + f1.x;
    z.y = xv.y + f0.y + f1.y;
    z.z = xv.z + f0.z + f1.z;
    z.w = xv.w + f0.w + f1.w;

    float s = z.x + z.y + z.z + z.w;
    float ss = z.x * z.x + z.y * z.y + z.z * z.z + z.w * z.w;
#pragma unroll
    for (int o = 16; o > 0; o >>= 1) {
        s += __shfl_xor_sync(0xffffffffu, s, o);
        ss += __shfl_xor_sync(0xffffffffu, ss, o);
    }
    __shared__ float sm[8];
    int w = tid >> 5;
    if ((tid & 31) == 0) { sm[w] = s; sm[4 + w] = ss; }
    __syncthreads();
    s = sm[0] + sm[1] + sm[2] + sm[3];
    ss = sm[4] + sm[5] + sm[6] + sm[7];

    float mean = s * (1.f / 512.f);
    float var = ss * (1.f / 512.f) - mean * mean;
    float rstd = rsqrtf(var + 1e-5f);

    float4 gv = *(const float4*)(gamma + tid * 4);
    float4 bv = *(const float4*)(beta + tid * 4);
    float4 o4;
    o4.x = (z.x - mean) * rstd * gv.x + bv.x;
    o4.y = (z.y - mean) * rstd * gv.y + bv.y;
    o4.z = (z.z - mean) * rstd * gv.z + bv.z;
    o4.w = (z.w - mean) * rstd * gv.w + bv.w;
    *(float4*)(out + off) = o4;
}

// ---------------------------------------------------------------------------
extern "C" void kernel_launch(void* const* d_in, const int* in_sizes, int n_in,
                              void* d_out, int out_size) {
    const float* x     = (const float*)d_in[0];
    const float* W1    = (const float*)d_in[1];
    const float* b1    = (const float*)d_in[2];
    const float* W2    = (const float*)d_in[3];
    const float* b2    = (const float*)d_in[4];
    const float* gamma = (const float*)d_in[5];
    const float* beta  = (const float*)d_in[6];
    const int*   orig  = (const int*)d_in[7];
    const int*   hmap  = (const int*)d_in[8];
    float* out = (float*)d_out;

    cudaFuncSetAttribute(gemm_kernel<true>, cudaFuncAttributeMaxDynamicSharedMemorySize, SMEM_BYTES);
    cudaFuncSetAttribute(gemm_kernel<false>, cudaFuncAttributeMaxDynamicSharedMemorySize, SMEM_BYTES);

    setup_kernel<<<1, 256>>>(orig, hmap);
    convert_x_kernel<<<(NW_X / 2 + 255) / 256, 256>>>(x);
    gemm_kernel<true><<<dim3(MAX_TILES, H_DIM / BN), NTHREADS, SMEM_BYTES>>>(W1, b1);
    gemm_kernel<false><<<dim3(MAX_TILES, D_DIM / BN, NSPLIT), NTHREADS, SMEM_BYTES>>>(W2, b2);
    ln_kernel<<<T_TOK, 128>>>(x, gamma, beta, out);
}